// round 12
// baseline (speedup 1.0000x reference)
#include <cuda_runtime.h>
#include <cuda_bf16.h>
#include <math_constants.h>
#include <cstdint>

#define HW 13
#define NTOK 169
#define BNP 192          // bf16 B-operand column stride
#define BATCH 256

typedef __nv_bfloat16 bf;

// ---- B-operand planes: [k][BNP] bf16, separate hi / lo ----
__device__ __align__(16) bf g_xh [BATCH * 512 * BNP], g_xl [BATCH * 512 * BNP];
__device__ __align__(16) bf g_f8h[BATCH * 256 * BNP], g_f8l[BATCH * 256 * BNP];
__device__ __align__(16) bf g_ph [BATCH * 128 * BNP], g_pl [BATCH * 128 * BNP];
__device__ __align__(16) bf g_Gh [BATCH * 64 * BNP],  g_Gl [BATCH * 64 * BNP];
__device__ __align__(16) bf g_Sh [BATCH * 192 * BNP], g_Sl [BATCH * 192 * BNP]; // rows 169+ stay 0
// ---- A-operand planes: [m][K] bf16 (row-major, K-contiguous) ----
__device__ __align__(16) bf g_fwh[64 * 512],  g_fwl[64 * 512];
__device__ __align__(16) bf g_gwh[64 * 512],  g_gwl[64 * 512];
__device__ __align__(16) bf g_hwh[192 * 256], g_hwl[192 * 256];
__device__ __align__(16) bf g_uwh[192 * 128], g_uwl[192 * 128];
__device__ __align__(16) bf g_cwh[512 * 192], g_cwl[512 * 192]; // cols 176+ stay 0
__device__ __align__(16) bf g_Fh [BATCH * 192 * 64], g_Fl[BATCH * 192 * 64];

// ============================================================
// low-level helpers
// ============================================================
__device__ __forceinline__ unsigned smem_u32(const void* p) {
    return (unsigned)__cvta_generic_to_shared(p);
}
__device__ __forceinline__ void cpa16(void* dst, const void* src) {
    asm volatile("cp.async.cg.shared.global [%0], [%1], 16;"
                 :: "r"(smem_u32(dst)), "l"(src));
}
#define CP_COMMIT()  asm volatile("cp.async.commit_group;")
#define CP_WAIT1()   asm volatile("cp.async.wait_group 1;")
#define CP_WAIT0()   asm volatile("cp.async.wait_group 0;")

__device__ __forceinline__ void ldsm_x4(unsigned (&r)[4], unsigned a) {
    asm volatile("ldmatrix.sync.aligned.m8n8.x4.shared.b16 {%0,%1,%2,%3}, [%4];"
        : "=r"(r[0]), "=r"(r[1]), "=r"(r[2]), "=r"(r[3]) : "r"(a));
}
__device__ __forceinline__ void ldsm_x4t(unsigned (&r)[4], unsigned a) {
    asm volatile("ldmatrix.sync.aligned.m8n8.x4.trans.shared.b16 {%0,%1,%2,%3}, [%4];"
        : "=r"(r[0]), "=r"(r[1]), "=r"(r[2]), "=r"(r[3]) : "r"(a));
}
__device__ __forceinline__ void mma16816(float (&d)[4], const unsigned (&a)[4],
                                         unsigned b0, unsigned b1) {
    asm volatile("mma.sync.aligned.m16n8k16.row.col.f32.bf16.bf16.f32 "
        "{%0,%1,%2,%3}, {%4,%5,%6,%7}, {%8,%9}, {%0,%1,%2,%3};"
        : "+f"(d[0]), "+f"(d[1]), "+f"(d[2]), "+f"(d[3])
        : "r"(a[0]), "r"(a[1]), "r"(a[2]), "r"(a[3]), "r"(b0), "r"(b1));
}
__device__ __forceinline__ void split_bf(float v, bf& hi, bf& lo) {
    hi = __float2bfloat16(v);
    lo = __float2bfloat16(v - __bfloat162float(hi));
}

// ============================================================
// GEMM machinery: CTA tile 64M x 192N (full N), warp grid 2M x 4N.
// Per warp: 32M x 48N -> acc[2][6][4] = 48 regs.
// Per k16 per warp: 4 A-ldsm + 6 B-ldsm feed 36 HMMA (fragment reuse).
// ============================================================
struct Smem {
    bf Ah[2][64][40];     // 10240 B per plane
    bf Al[2][64][40];
    bf Bh[2][32][200];    // 25600 B per plane (192 cols + pad 8)
    bf Bl[2][32][200];
};                         // total 71680 B
#define SMEM_BYTES sizeof(Smem)

__device__ __forceinline__ void fill(Smem& s, int buf,
                                     const bf* __restrict__ Ah, const bf* __restrict__ Al,
                                     int lda,
                                     const bf* __restrict__ Bh, const bf* __restrict__ Bl,
                                     int k0, int tid)
{
#pragma unroll
    for (int i = 0; i < 2; i++) {       // A: 512 x 16B units
        int idx = tid + i * 256;
        int var = idx >> 8;
        int j = idx & 255;
        int r = j >> 2, q = j & 3;
        const bf* src = (var ? Al : Ah) + (size_t)r * lda + k0 + q * 8;
        bf* dst = var ? &s.Al[buf][r][q * 8] : &s.Ah[buf][r][q * 8];
        cpa16(dst, src);
    }
#pragma unroll
    for (int i = 0; i < 6; i++) {       // B: 1536 x 16B units (32 rows x 192 cols x 2 planes)
        int idx = tid + i * 256;
        int var = idx >= 768;
        int j = idx - (var ? 768 : 0);
        int rr = j / 24, q = j - rr * 24;
        const bf* src = (var ? Bl : Bh) + (size_t)(k0 + rr) * BNP + q * 8;
        bf* dst = var ? &s.Bl[buf][rr][q * 8] : &s.Bh[buf][rr][q * 8];
        cpa16(dst, src);
    }
}

__device__ __forceinline__ void mma_chunk(float (&acc)[2][6][4], Smem& s, int buf,
                                          int lane, int wm, int wn)
{
    unsigned rsel = lane & 15;
    unsigned csel = (lane >> 4) << 3;
#pragma unroll
    for (int ks = 0; ks < 32; ks += 16) {
        unsigned ah[2][4], al[2][4];
#pragma unroll
        for (int mt = 0; mt < 2; mt++) {
            ldsm_x4(ah[mt], smem_u32(&s.Ah[buf][wm * 32 + mt * 16 + rsel][ks + csel]));
            ldsm_x4(al[mt], smem_u32(&s.Al[buf][wm * 32 + mt * 16 + rsel][ks + csel]));
        }
#pragma unroll
        for (int g = 0; g < 3; g++) {
            unsigned bh[4], bl[4];
            ldsm_x4t(bh, smem_u32(&s.Bh[buf][ks + rsel][wn * 48 + g * 16 + csel]));
            ldsm_x4t(bl, smem_u32(&s.Bl[buf][ks + rsel][wn * 48 + g * 16 + csel]));
#pragma unroll
            for (int mt = 0; mt < 2; mt++) {
                mma16816(acc[mt][2 * g],     ah[mt], bh[0], bh[1]);
                mma16816(acc[mt][2 * g],     ah[mt], bl[0], bl[1]);
                mma16816(acc[mt][2 * g],     al[mt], bh[0], bh[1]);
                mma16816(acc[mt][2 * g + 1], ah[mt], bh[2], bh[3]);
                mma16816(acc[mt][2 * g + 1], ah[mt], bl[2], bl[3]);
                mma16816(acc[mt][2 * g + 1], al[mt], bh[2], bh[3]);
            }
        }
    }
}

__device__ __forceinline__ void run_gemm(Smem& s, float (&acc)[2][6][4],
                                         const bf* __restrict__ Ah, const bf* __restrict__ Al,
                                         int lda,
                                         const bf* __restrict__ Bh, const bf* __restrict__ Bl,
                                         int K, int tid, int lane, int wm, int wn)
{
    int nt = K >> 5;
    fill(s, 0, Ah, Al, lda, Bh, Bl, 0, tid);
    CP_COMMIT();
    for (int t = 0; t < nt; t++) {
        if (t + 1 < nt) {
            fill(s, (t + 1) & 1, Ah, Al, lda, Bh, Bl, (t + 1) * 32, tid);
            CP_COMMIT();
            CP_WAIT1();
        } else {
            CP_WAIT0();
        }
        __syncthreads();
        mma_chunk(acc, s, t & 1, lane, wm, wn);
        __syncthreads();
    }
}

// ============================================================
// split / repack kernels
// ============================================================
__global__ __launch_bounds__(256) void split_w_kernel(
    const float* __restrict__ f_w, const float* __restrict__ g_w,
    const float* __restrict__ h_w, const float* __restrict__ u_w,
    const float* __restrict__ c_w)
{
    int idx = blockIdx.x * 256 + threadIdx.x;
    float v; bf *dh, *dl;
    if (idx < 64 * 512) {
        v = f_w[idx]; dh = g_fwh + idx; dl = g_fwl + idx;
    } else if ((idx -= 64 * 512) < 64 * 512) {
        v = g_w[idx]; dh = g_gwh + idx; dl = g_gwl + idx;
    } else if ((idx -= 64 * 512) < 169 * 256) {
        v = h_w[idx]; dh = g_hwh + idx; dl = g_hwl + idx;
    } else if ((idx -= 169 * 256) < 169 * 128) {
        v = u_w[idx]; dh = g_uwh + idx; dl = g_uwl + idx;
    } else if ((idx -= 169 * 128) < 512 * 169) {
        int m = idx / 169, k = idx - m * 169;
        v = c_w[idx];
        dh = g_cwh + (size_t)m * 192 + k; dl = g_cwl + (size_t)m * 192 + k;
    } else return;
    bf hi, lo; split_bf(v, hi, lo);
    *dh = hi; *dl = lo;
}

#define XE (BATCH * 512 * NTOK)
#define FE (BATCH * 256 * NTOK)
__global__ __launch_bounds__(256) void split_x_kernel(const float* __restrict__ x,
                                                      const float* __restrict__ f8)
{
    int idx = blockIdx.x * 256 + threadIdx.x;
    const float* src; bf *bh, *bl;
    if (idx < XE)              { src = x;  bh = g_xh;  bl = g_xl; }
    else if ((idx -= XE) < FE) { src = f8; bh = g_f8h; bl = g_f8l; }
    else return;
    int row = idx / NTOK, n = idx - row * NTOK;
    bf hi, lo; split_bf(src[idx], hi, lo);
    size_t o = (size_t)row * BNP + n;
    bh[o] = hi; bl[o] = lo;
}

// ============================================================
// antialiased bilinear 26 -> 13 (jax antialias=True), writes split bf16
// ============================================================
__constant__ int   c_tap0[HW] = { 0, 1, 3, 5, 7, 9,11,13,15,17,19,21,23};
__constant__ float c_wt[HW][4] = {
    {3.f/7.f, 3.f/7.f, 1.f/7.f, 0.f},
    {0.125f, 0.375f, 0.375f, 0.125f}, {0.125f, 0.375f, 0.375f, 0.125f},
    {0.125f, 0.375f, 0.375f, 0.125f}, {0.125f, 0.375f, 0.375f, 0.125f},
    {0.125f, 0.375f, 0.375f, 0.125f}, {0.125f, 0.375f, 0.375f, 0.125f},
    {0.125f, 0.375f, 0.375f, 0.125f}, {0.125f, 0.375f, 0.375f, 0.125f},
    {0.125f, 0.375f, 0.375f, 0.125f}, {0.125f, 0.375f, 0.375f, 0.125f},
    {0.125f, 0.375f, 0.375f, 0.125f},
    {1.f/7.f, 3.f/7.f, 3.f/7.f, 0.f}
};

__global__ __launch_bounds__(256) void pool_kernel(const float* __restrict__ f5) {
    int idx = blockIdx.x * blockDim.x + threadIdx.x;
    if (idx >= BATCH * 128 * NTOK) return;
    int n  = idx % NTOK;
    int bc = idx / NTOK;
    int j = n % HW, i = n / HW;
    const float* src = f5 + (size_t)bc * 26 * 26;
    int r0 = c_tap0[i], cc0 = c_tap0[j];
    float acc = 0.f;
#pragma unroll
    for (int ri = 0; ri < 4; ri++) {
        float wr = c_wt[i][ri];
        if (wr == 0.f) continue;
        int r = r0 + ri;
        float rowv = 0.f;
#pragma unroll
        for (int ci = 0; ci < 4; ci++) {
            float wc = c_wt[j][ci];
            if (wc == 0.f) continue;
            rowv = fmaf(wc, src[r * 26 + cc0 + ci], rowv);
        }
        acc = fmaf(wr, rowv, acc);
    }
    bf hi, lo; split_bf(acc, hi, lo);
    size_t o = (size_t)bc * BNP + n;
    g_ph[o] = hi; g_pl[o] = lo;
}

// ============================================================
// F / G projections: grid (2, BATCH)
// ============================================================
__global__ __launch_bounds__(256, 2) void fg_kernel(const float* __restrict__ f_b,
                                                    const float* __restrict__ g_b)
{
    extern __shared__ char smem_raw[];
    Smem& s = *reinterpret_cast<Smem*>(smem_raw);
    int b    = blockIdx.y;
    bool isG = blockIdx.x != 0;
    int tid = threadIdx.x, lane = tid & 31, wid = tid >> 5;
    int wm = wid & 1, wn = wid >> 1;

    float acc[2][6][4] = {};
    run_gemm(s, acc, isG ? g_gwh : g_fwh, isG ? g_gwl : g_fwl, 512,
             g_xh + (size_t)b * 512 * BNP, g_xl + (size_t)b * 512 * BNP, 512,
             tid, lane, wm, wn);

    const float* bias = isG ? g_b : f_b;
    int lr = lane >> 2, lc = (lane & 3) * 2;
#pragma unroll
    for (int mt = 0; mt < 2; mt++)
#pragma unroll
    for (int half = 0; half < 2; half++) {
        int m = wm * 32 + mt * 16 + lr + half * 8;
        float bv = bias[m];
#pragma unroll
        for (int t = 0; t < 6; t++) {
#pragma unroll
            for (int e = 0; e < 2; e++) {
                int n = wn * 48 + t * 8 + lc + e;
                if (n >= NTOK) continue;
                float v = acc[mt][t][half * 2 + e] + bv;
                bf hi, lo; split_bf(v, hi, lo);
                if (isG) {
                    size_t o = (size_t)(b * 64 + m) * BNP + n;
                    g_Gh[o] = hi; g_Gl[o] = lo;
                } else {
                    size_t o = (size_t)(b * 192 + n) * 64 + m;
                    g_Fh[o] = hi; g_Fl[o] = lo;
                }
            }
        }
    }
}

// ============================================================
// S = softmax(F^T G) + h_w@f8 + u_w@pool + bias     grid (3, BATCH)
// ============================================================
__global__ __launch_bounds__(256, 2) void s_kernel(const float* __restrict__ h_b,
                                                   const float* __restrict__ u_b)
{
    extern __shared__ char smem_raw[];
    Smem& s = *reinterpret_cast<Smem*>(smem_raw);
    __shared__ float redM[4][64], redS[4][64];
    int b   = blockIdx.y;
    int m0  = blockIdx.x * 64;
    int tid = threadIdx.x, lane = tid & 31, wid = tid >> 5;
    int wm = wid & 1, wn = wid >> 1;
    int lr = lane >> 2, lc = (lane & 3) * 2;

    float acc[2][6][4] = {};

    // energy = F^T G  (K = 64)
    run_gemm(s, acc, g_Fh + (size_t)(b * 192 + m0) * 64,
                     g_Fl + (size_t)(b * 192 + m0) * 64, 64,
             g_Gh + (size_t)b * 64 * BNP, g_Gl + (size_t)b * 64 * BNP, 64,
             tid, lane, wm, wn);

    // ---- softmax over cols (rows split across 4 N-warps, 4 lanes each) ----
    float pmax[2][2];
#pragma unroll
    for (int mt = 0; mt < 2; mt++)
#pragma unroll
        for (int half = 0; half < 2; half++) {
            float m = -CUDART_INF_F;
#pragma unroll
            for (int t = 0; t < 6; t++)
#pragma unroll
                for (int e = 0; e < 2; e++) {
                    int n = wn * 48 + t * 8 + lc + e;
                    if (n < NTOK) m = fmaxf(m, acc[mt][t][half * 2 + e]);
                }
            pmax[mt][half] = m;
        }
#pragma unroll
    for (int off = 1; off < 4; off <<= 1)
#pragma unroll
        for (int mt = 0; mt < 2; mt++)
#pragma unroll
            for (int half = 0; half < 2; half++)
                pmax[mt][half] = fmaxf(pmax[mt][half],
                    __shfl_xor_sync(0xffffffffu, pmax[mt][half], off, 4));
    if ((lane & 3) == 0) {
#pragma unroll
        for (int mt = 0; mt < 2; mt++)
#pragma unroll
            for (int half = 0; half < 2; half++)
                redM[wn][wm * 32 + mt * 16 + lr + half * 8] = pmax[mt][half];
    }
    __syncthreads();
    float mx[2][2];
#pragma unroll
    for (int mt = 0; mt < 2; mt++)
#pragma unroll
        for (int half = 0; half < 2; half++) {
            int row = wm * 32 + mt * 16 + lr + half * 8;
            mx[mt][half] = fmaxf(fmaxf(redM[0][row], redM[1][row]),
                                 fmaxf(redM[2][row], redM[3][row]));
        }
    float psum[2][2] = {};
#pragma unroll
    for (int mt = 0; mt < 2; mt++)
#pragma unroll
        for (int half = 0; half < 2; half++)
#pragma unroll
            for (int t = 0; t < 6; t++)
#pragma unroll
                for (int e = 0; e < 2; e++) {
                    int n = wn * 48 + t * 8 + lc + e;
                    float ev = (n < NTOK) ?
                        __expf(acc[mt][t][half * 2 + e] - mx[mt][half]) : 0.f;
                    acc[mt][t][half * 2 + e] = ev;
                    psum[mt][half] += ev;
                }
#pragma unroll
    for (int off = 1; off < 4; off <<= 1)
#pragma unroll
        for (int mt = 0; mt < 2; mt++)
#pragma unroll
            for (int half = 0; half < 2; half++)
                psum[mt][half] += __shfl_xor_sync(0xffffffffu, psum[mt][half], off, 4);
    if ((lane & 3) == 0) {
#pragma unroll
        for (int mt = 0; mt < 2; mt++)
#pragma unroll
            for (int half = 0; half < 2; half++)
                redS[wn][wm * 32 + mt * 16 + lr + half * 8] = psum[mt][half];
    }
    __syncthreads();
#pragma unroll
    for (int mt = 0; mt < 2; mt++)
#pragma unroll
        for (int half = 0; half < 2; half++) {
            int row = wm * 32 + mt * 16 + lr + half * 8;
            float inv = 1.f / (redS[0][row] + redS[1][row] + redS[2][row] + redS[3][row]);
#pragma unroll
            for (int t = 0; t < 6; t++)
#pragma unroll
                for (int e = 0; e < 2; e++)
                    acc[mt][t][half * 2 + e] *= inv;
        }
    __syncthreads();

    // += h_w @ f8 (K=256), += u_w @ pool (K=128)
    run_gemm(s, acc, g_hwh + (size_t)m0 * 256, g_hwl + (size_t)m0 * 256, 256,
             g_f8h + (size_t)b * 256 * BNP, g_f8l + (size_t)b * 256 * BNP, 256,
             tid, lane, wm, wn);
    run_gemm(s, acc, g_uwh + (size_t)m0 * 128, g_uwl + (size_t)m0 * 128, 128,
             g_ph + (size_t)b * 128 * BNP, g_pl + (size_t)b * 128 * BNP, 128,
             tid, lane, wm, wn);

    // ---- write split S planes ----
#pragma unroll
    for (int mt = 0; mt < 2; mt++)
#pragma unroll
    for (int half = 0; half < 2; half++) {
        int row = m0 + wm * 32 + mt * 16 + lr + half * 8;
        if (row >= NTOK) continue;
        float bv = h_b[row] + u_b[row];
        size_t ro = (size_t)(b * 192 + row) * BNP;
#pragma unroll
        for (int t = 0; t < 6; t++)
#pragma unroll
            for (int e = 0; e < 2; e++) {
                int n = wn * 48 + t * 8 + lc + e;
                if (n < NTOK) {
                    bf hi, lo; split_bf(acc[mt][t][half * 2 + e] + bv, hi, lo);
                    g_Sh[ro + n] = hi; g_Sl[ro + n] = lo;
                }
            }
    }
}

// ============================================================
// out = gamma * (c_w @ S + c_b) + x     grid (8, BATCH), K = 192
// ============================================================
__global__ __launch_bounds__(256, 2) void out_kernel(const float* __restrict__ c_b,
                                                     const float* __restrict__ x,
                                                     const float* __restrict__ gamma_p,
                                                     float* __restrict__ Out)
{
    extern __shared__ char smem_raw[];
    Smem& s = *reinterpret_cast<Smem*>(smem_raw);
    int b   = blockIdx.y;
    int m0  = blockIdx.x * 64;
    int tid = threadIdx.x, lane = tid & 31, wid = tid >> 5;
    int wm = wid & 1, wn = wid >> 1;
    int lr = lane >> 2, lc = (lane & 3) * 2;

    float acc[2][6][4] = {};
    run_gemm(s, acc, g_cwh + (size_t)m0 * 192, g_cwl + (size_t)m0 * 192, 192,
             g_Sh + (size_t)b * 192 * BNP, g_Sl + (size_t)b * 192 * BNP, 192,
             tid, lane, wm, wn);

    float gma = *gamma_p;
#pragma unroll
    for (int mt = 0; mt < 2; mt++)
#pragma unroll
    for (int half = 0; half < 2; half++) {
        int m = m0 + wm * 32 + mt * 16 + lr + half * 8;
        float bv = c_b[m];
        const float* xrow = x + (size_t)b * 512 * NTOK + (size_t)m * NTOK;
        float* orow = Out + (size_t)b * 512 * NTOK + (size_t)m * NTOK;
#pragma unroll
        for (int t = 0; t < 6; t++)
#pragma unroll
            for (int e = 0; e < 2; e++) {
                int n = wn * 48 + t * 8 + lc + e;
                if (n < NTOK)
                    orow[n] = fmaf(gma, acc[mt][t][half * 2 + e] + bv, xrow[n]);
            }
    }
}

// ============================================================
extern "C" void kernel_launch(void* const* d_in, const int* in_sizes, int n_in,
                              void* d_out, int out_size)
{
    const float* x    = (const float*)d_in[0];
    const float* f5   = (const float*)d_in[1];
    const float* f8   = (const float*)d_in[2];
    const float* f_w  = (const float*)d_in[3];
    const float* f_b  = (const float*)d_in[4];
    const float* g_w  = (const float*)d_in[5];
    const float* g_b  = (const float*)d_in[6];
    const float* h_w  = (const float*)d_in[7];
    const float* h_b  = (const float*)d_in[8];
    const float* u_w  = (const float*)d_in[9];
    const float* u_b  = (const float*)d_in[10];
    const float* c_w  = (const float*)d_in[11];
    const float* c_b  = (const float*)d_in[12];
    const float* gma  = (const float*)d_in[13];

    float* out = (float*)d_out;

    cudaFuncSetAttribute(fg_kernel,  cudaFuncAttributeMaxDynamicSharedMemorySize, (int)SMEM_BYTES);
    cudaFuncSetAttribute(s_kernel,   cudaFuncAttributeMaxDynamicSharedMemorySize, (int)SMEM_BYTES);
    cudaFuncSetAttribute(out_kernel, cudaFuncAttributeMaxDynamicSharedMemorySize, (int)SMEM_BYTES);

    int wtot = 2 * 64 * 512 + 169 * 256 + 169 * 128 + 512 * 169;
    split_w_kernel<<<(wtot + 255) / 256, 256>>>(f_w, g_w, h_w, u_w, c_w);
    split_x_kernel<<<(XE + FE + 255) / 256, 256>>>(x, f8);
    {
        int total = BATCH * 128 * NTOK;
        pool_kernel<<<(total + 255) / 256, 256>>>(f5);
    }
    fg_kernel<<<dim3(2, BATCH), 256, SMEM_BYTES>>>(f_b, g_b);
    s_kernel<<<dim3(3, BATCH), 256, SMEM_BYTES>>>(h_b, u_b);
    out_kernel<<<dim3(8, BATCH), 256, SMEM_BYTES>>>(c_b, x, gma, out);
}

// round 13
// speedup vs baseline: 1.1835x; 1.1835x over previous
#include <cuda_runtime.h>
#include <cuda_fp16.h>
#include <math_constants.h>
#include <cstdint>

#define HW 13
#define NTOK 169
#define BNP 192          // fp16 B-operand column stride
#define BATCH 256

typedef __half hf;

// ---- B-operand planes (hi only): [k][BNP] fp16 ----
__device__ __align__(16) hf g_xh [BATCH * 512 * BNP];
__device__ __align__(16) hf g_f8h[BATCH * 256 * BNP];
__device__ __align__(16) hf g_ph [BATCH * 128 * BNP];
__device__ __align__(16) hf g_Gh [BATCH * 64 * BNP];
__device__ __align__(16) hf g_Sh [BATCH * 192 * BNP];   // rows 169+ stay 0
// ---- A-operand planes: [m][K] fp16 hi + lo (full precision A) ----
__device__ __align__(16) hf g_fwh[64 * 512],  g_fwl[64 * 512];
__device__ __align__(16) hf g_gwh[64 * 512],  g_gwl[64 * 512];
__device__ __align__(16) hf g_hwh[192 * 256], g_hwl[192 * 256];
__device__ __align__(16) hf g_uwh[192 * 128], g_uwl[192 * 128];
__device__ __align__(16) hf g_cwh[512 * 192], g_cwl[512 * 192]; // cols 176+ stay 0
__device__ __align__(16) hf g_Fh [BATCH * 192 * 64], g_Fl[BATCH * 192 * 64];

// ============================================================
// low-level helpers
// ============================================================
__device__ __forceinline__ unsigned smem_u32(const void* p) {
    return (unsigned)__cvta_generic_to_shared(p);
}
__device__ __forceinline__ void cpa16(void* dst, const void* src) {
    asm volatile("cp.async.cg.shared.global [%0], [%1], 16;"
                 :: "r"(smem_u32(dst)), "l"(src));
}
#define CP_COMMIT()  asm volatile("cp.async.commit_group;")
#define CP_WAIT1()   asm volatile("cp.async.wait_group 1;")
#define CP_WAIT0()   asm volatile("cp.async.wait_group 0;")

__device__ __forceinline__ void ldsm_x4(unsigned (&r)[4], unsigned a) {
    asm volatile("ldmatrix.sync.aligned.m8n8.x4.shared.b16 {%0,%1,%2,%3}, [%4];"
        : "=r"(r[0]), "=r"(r[1]), "=r"(r[2]), "=r"(r[3]) : "r"(a));
}
__device__ __forceinline__ void ldsm_x4t(unsigned (&r)[4], unsigned a) {
    asm volatile("ldmatrix.sync.aligned.m8n8.x4.trans.shared.b16 {%0,%1,%2,%3}, [%4];"
        : "=r"(r[0]), "=r"(r[1]), "=r"(r[2]), "=r"(r[3]) : "r"(a));
}
__device__ __forceinline__ void mma16816(float (&d)[4], const unsigned (&a)[4],
                                         unsigned b0, unsigned b1) {
    asm volatile("mma.sync.aligned.m16n8k16.row.col.f32.f16.f16.f32 "
        "{%0,%1,%2,%3}, {%4,%5,%6,%7}, {%8,%9}, {%0,%1,%2,%3};"
        : "+f"(d[0]), "+f"(d[1]), "+f"(d[2]), "+f"(d[3])
        : "r"(a[0]), "r"(a[1]), "r"(a[2]), "r"(a[3]), "r"(b0), "r"(b1));
}
__device__ __forceinline__ void split_h(float v, hf& hi, hf& lo) {
    hi = __float2half_rn(v);
    lo = __float2half_rn(v - __half2float(hi));
}

// ============================================================
// GEMM: CTA tile 64M x 192N, warp grid 2M x 4N (32M x 48N per warp).
// 2-term split: D = (Ah + Al) * Bh. Per k16/warp: 7 LDSM, 24 HMMA.
// ============================================================
struct Smem {
    hf Ah[2][64][40];     // 10240 B
    hf Al[2][64][40];     // 10240 B
    hf Bh[2][32][200];    // 25600 B
};                         // 46080 B total
#define SMEM_BYTES sizeof(Smem)

__device__ __forceinline__ void fill(Smem& s, int buf,
                                     const hf* __restrict__ Ah, const hf* __restrict__ Al,
                                     int lda, const hf* __restrict__ Bh,
                                     int k0, int tid)
{
#pragma unroll
    for (int i = 0; i < 5; i++) {       // 512 A-units + 768 B-units = 1280 16B ops
        int idx = tid + i * 256;
        if (idx < 512) {
            int var = idx >> 8;
            int j = idx & 255;
            int r = j >> 2, q = j & 3;
            const hf* src = (var ? Al : Ah) + (size_t)r * lda + k0 + q * 8;
            hf* dst = var ? &s.Al[buf][r][q * 8] : &s.Ah[buf][r][q * 8];
            cpa16(dst, src);
        } else {
            int j = idx - 512;
            int rr = j / 24, q = j - rr * 24;
            cpa16(&s.Bh[buf][rr][q * 8], Bh + (size_t)(k0 + rr) * BNP + q * 8);
        }
    }
}

__device__ __forceinline__ void mma_chunk(float (&acc)[2][6][4], Smem& s, int buf,
                                          int lane, int wm, int wn)
{
    unsigned rsel = lane & 15;
    unsigned csel = (lane >> 4) << 3;
#pragma unroll
    for (int ks = 0; ks < 32; ks += 16) {
        unsigned ah[2][4], al[2][4];
#pragma unroll
        for (int mt = 0; mt < 2; mt++) {
            ldsm_x4(ah[mt], smem_u32(&s.Ah[buf][wm * 32 + mt * 16 + rsel][ks + csel]));
            ldsm_x4(al[mt], smem_u32(&s.Al[buf][wm * 32 + mt * 16 + rsel][ks + csel]));
        }
#pragma unroll
        for (int g = 0; g < 3; g++) {
            unsigned bh[4];
            ldsm_x4t(bh, smem_u32(&s.Bh[buf][ks + rsel][wn * 48 + g * 16 + csel]));
#pragma unroll
            for (int mt = 0; mt < 2; mt++) {
                mma16816(acc[mt][2 * g],     ah[mt], bh[0], bh[1]);
                mma16816(acc[mt][2 * g],     al[mt], bh[0], bh[1]);
                mma16816(acc[mt][2 * g + 1], ah[mt], bh[2], bh[3]);
                mma16816(acc[mt][2 * g + 1], al[mt], bh[2], bh[3]);
            }
        }
    }
}

__device__ __forceinline__ void run_gemm(Smem& s, float (&acc)[2][6][4],
                                         const hf* __restrict__ Ah, const hf* __restrict__ Al,
                                         int lda, const hf* __restrict__ Bh,
                                         int K, int tid, int lane, int wm, int wn)
{
    int nt = K >> 5;
    fill(s, 0, Ah, Al, lda, Bh, 0, tid);
    CP_COMMIT();
    for (int t = 0; t < nt; t++) {
        if (t + 1 < nt) {
            fill(s, (t + 1) & 1, Ah, Al, lda, Bh, (t + 1) * 32, tid);
            CP_COMMIT();
            CP_WAIT1();
        } else {
            CP_WAIT0();
        }
        __syncthreads();
        mma_chunk(acc, s, t & 1, lane, wm, wn);
        __syncthreads();
    }
}

// ============================================================
// split / repack kernels
// ============================================================
__global__ __launch_bounds__(256) void split_w_kernel(
    const float* __restrict__ f_w, const float* __restrict__ g_w,
    const float* __restrict__ h_w, const float* __restrict__ u_w,
    const float* __restrict__ c_w)
{
    int idx = blockIdx.x * 256 + threadIdx.x;
    float v; hf *dh, *dl;
    if (idx < 64 * 512) {
        v = f_w[idx]; dh = g_fwh + idx; dl = g_fwl + idx;
    } else if ((idx -= 64 * 512) < 64 * 512) {
        v = g_w[idx]; dh = g_gwh + idx; dl = g_gwl + idx;
    } else if ((idx -= 64 * 512) < 169 * 256) {
        v = h_w[idx]; dh = g_hwh + idx; dl = g_hwl + idx;
    } else if ((idx -= 169 * 256) < 169 * 128) {
        v = u_w[idx]; dh = g_uwh + idx; dl = g_uwl + idx;
    } else if ((idx -= 169 * 128) < 512 * 169) {
        int m = idx / 169, k = idx - m * 169;
        v = c_w[idx];
        dh = g_cwh + (size_t)m * 192 + k; dl = g_cwl + (size_t)m * 192 + k;
    } else return;
    hf hi, lo; split_h(v, hi, lo);
    *dh = hi; *dl = lo;
}

#define XE (BATCH * 512 * NTOK)
#define FE (BATCH * 256 * NTOK)
__global__ __launch_bounds__(256) void split_x_kernel(const float* __restrict__ x,
                                                      const float* __restrict__ f8)
{
    int idx = blockIdx.x * 256 + threadIdx.x;
    const float* src; hf* bh;
    if (idx < XE)              { src = x;  bh = g_xh; }
    else if ((idx -= XE) < FE) { src = f8; bh = g_f8h; }
    else return;
    int row = idx / NTOK, n = idx - row * NTOK;
    bh[(size_t)row * BNP + n] = __float2half_rn(src[idx]);
}

// ============================================================
// antialiased bilinear 26 -> 13 (jax antialias=True)
// ============================================================
__constant__ int   c_tap0[HW] = { 0, 1, 3, 5, 7, 9,11,13,15,17,19,21,23};
__constant__ float c_wt[HW][4] = {
    {3.f/7.f, 3.f/7.f, 1.f/7.f, 0.f},
    {0.125f, 0.375f, 0.375f, 0.125f}, {0.125f, 0.375f, 0.375f, 0.125f},
    {0.125f, 0.375f, 0.375f, 0.125f}, {0.125f, 0.375f, 0.375f, 0.125f},
    {0.125f, 0.375f, 0.375f, 0.125f}, {0.125f, 0.375f, 0.375f, 0.125f},
    {0.125f, 0.375f, 0.375f, 0.125f}, {0.125f, 0.375f, 0.375f, 0.125f},
    {0.125f, 0.375f, 0.375f, 0.125f}, {0.125f, 0.375f, 0.375f, 0.125f},
    {0.125f, 0.375f, 0.375f, 0.125f},
    {1.f/7.f, 3.f/7.f, 3.f/7.f, 0.f}
};

__global__ __launch_bounds__(256) void pool_kernel(const float* __restrict__ f5) {
    int idx = blockIdx.x * blockDim.x + threadIdx.x;
    if (idx >= BATCH * 128 * NTOK) return;
    int n  = idx % NTOK;
    int bc = idx / NTOK;
    int j = n % HW, i = n / HW;
    const float* src = f5 + (size_t)bc * 26 * 26;
    int r0 = c_tap0[i], cc0 = c_tap0[j];
    float acc = 0.f;
#pragma unroll
    for (int ri = 0; ri < 4; ri++) {
        float wr = c_wt[i][ri];
        if (wr == 0.f) continue;
        int r = r0 + ri;
        float rowv = 0.f;
#pragma unroll
        for (int ci = 0; ci < 4; ci++) {
            float wc = c_wt[j][ci];
            if (wc == 0.f) continue;
            rowv = fmaf(wc, src[r * 26 + cc0 + ci], rowv);
        }
        acc = fmaf(wr, rowv, acc);
    }
    g_ph[(size_t)bc * BNP + n] = __float2half_rn(acc);
}

// ============================================================
// F / G projections: grid (2, BATCH)
// ============================================================
__global__ __launch_bounds__(256, 2) void fg_kernel(const float* __restrict__ f_b,
                                                    const float* __restrict__ g_b)
{
    extern __shared__ char smem_raw[];
    Smem& s = *reinterpret_cast<Smem*>(smem_raw);
    int b    = blockIdx.y;
    bool isG = blockIdx.x != 0;
    int tid = threadIdx.x, lane = tid & 31, wid = tid >> 5;
    int wm = wid & 1, wn = wid >> 1;

    float acc[2][6][4] = {};
    run_gemm(s, acc, isG ? g_gwh : g_fwh, isG ? g_gwl : g_fwl, 512,
             g_xh + (size_t)b * 512 * BNP, 512, tid, lane, wm, wn);

    const float* bias = isG ? g_b : f_b;
    int lr = lane >> 2, lc = (lane & 3) * 2;
#pragma unroll
    for (int mt = 0; mt < 2; mt++)
#pragma unroll
    for (int half = 0; half < 2; half++) {
        int m = wm * 32 + mt * 16 + lr + half * 8;
        float bv = bias[m];
#pragma unroll
        for (int t = 0; t < 6; t++) {
#pragma unroll
            for (int e = 0; e < 2; e++) {
                int n = wn * 48 + t * 8 + lc + e;
                if (n >= NTOK) continue;
                float v = acc[mt][t][half * 2 + e] + bv;
                if (isG) {
                    g_Gh[(size_t)(b * 64 + m) * BNP + n] = __float2half_rn(v);
                } else {
                    hf hi, lo; split_h(v, hi, lo);
                    size_t o = (size_t)(b * 192 + n) * 64 + m;
                    g_Fh[o] = hi; g_Fl[o] = lo;
                }
            }
        }
    }
}

// ============================================================
// S = softmax(F^T G) + h_w@f8 + u_w@pool + bias     grid (3, BATCH)
// ============================================================
__global__ __launch_bounds__(256, 2) void s_kernel(const float* __restrict__ h_b,
                                                   const float* __restrict__ u_b)
{
    extern __shared__ char smem_raw[];
    Smem& s = *reinterpret_cast<Smem*>(smem_raw);
    __shared__ float redM[4][64], redS[4][64];
    int b   = blockIdx.y;
    int m0  = blockIdx.x * 64;
    int tid = threadIdx.x, lane = tid & 31, wid = tid >> 5;
    int wm = wid & 1, wn = wid >> 1;
    int lr = lane >> 2, lc = (lane & 3) * 2;

    float acc[2][6][4] = {};

    // energy = F^T G  (K = 64)
    run_gemm(s, acc, g_Fh + (size_t)(b * 192 + m0) * 64,
                     g_Fl + (size_t)(b * 192 + m0) * 64, 64,
             g_Gh + (size_t)b * 64 * BNP, 64, tid, lane, wm, wn);

    // ---- softmax over cols ----
    float pmax[2][2];
#pragma unroll
    for (int mt = 0; mt < 2; mt++)
#pragma unroll
        for (int half = 0; half < 2; half++) {
            float m = -CUDART_INF_F;
#pragma unroll
            for (int t = 0; t < 6; t++)
#pragma unroll
                for (int e = 0; e < 2; e++) {
                    int n = wn * 48 + t * 8 + lc + e;
                    if (n < NTOK) m = fmaxf(m, acc[mt][t][half * 2 + e]);
                }
            pmax[mt][half] = m;
        }
#pragma unroll
    for (int off = 1; off < 4; off <<= 1)
#pragma unroll
        for (int mt = 0; mt < 2; mt++)
#pragma unroll
            for (int half = 0; half < 2; half++)
                pmax[mt][half] = fmaxf(pmax[mt][half],
                    __shfl_xor_sync(0xffffffffu, pmax[mt][half], off, 4));
    if ((lane & 3) == 0) {
#pragma unroll
        for (int mt = 0; mt < 2; mt++)
#pragma unroll
            for (int half = 0; half < 2; half++)
                redM[wn][wm * 32 + mt * 16 + lr + half * 8] = pmax[mt][half];
    }
    __syncthreads();
    float mx[2][2];
#pragma unroll
    for (int mt = 0; mt < 2; mt++)
#pragma unroll
        for (int half = 0; half < 2; half++) {
            int row = wm * 32 + mt * 16 + lr + half * 8;
            mx[mt][half] = fmaxf(fmaxf(redM[0][row], redM[1][row]),
                                 fmaxf(redM[2][row], redM[3][row]));
        }
    float psum[2][2] = {};
#pragma unroll
    for (int mt = 0; mt < 2; mt++)
#pragma unroll
        for (int half = 0; half < 2; half++)
#pragma unroll
            for (int t = 0; t < 6; t++)
#pragma unroll
                for (int e = 0; e < 2; e++) {
                    int n = wn * 48 + t * 8 + lc + e;
                    float ev = (n < NTOK) ?
                        __expf(acc[mt][t][half * 2 + e] - mx[mt][half]) : 0.f;
                    acc[mt][t][half * 2 + e] = ev;
                    psum[mt][half] += ev;
                }
#pragma unroll
    for (int off = 1; off < 4; off <<= 1)
#pragma unroll
        for (int mt = 0; mt < 2; mt++)
#pragma unroll
            for (int half = 0; half < 2; half++)
                psum[mt][half] += __shfl_xor_sync(0xffffffffu, psum[mt][half], off, 4);
    if ((lane & 3) == 0) {
#pragma unroll
        for (int mt = 0; mt < 2; mt++)
#pragma unroll
            for (int half = 0; half < 2; half++)
                redS[wn][wm * 32 + mt * 16 + lr + half * 8] = psum[mt][half];
    }
    __syncthreads();
#pragma unroll
    for (int mt = 0; mt < 2; mt++)
#pragma unroll
        for (int half = 0; half < 2; half++) {
            int row = wm * 32 + mt * 16 + lr + half * 8;
            float inv = 1.f / (redS[0][row] + redS[1][row] + redS[2][row] + redS[3][row]);
#pragma unroll
            for (int t = 0; t < 6; t++)
#pragma unroll
                for (int e = 0; e < 2; e++)
                    acc[mt][t][half * 2 + e] *= inv;
        }
    __syncthreads();

    // += h_w @ f8 (K=256), += u_w @ pool (K=128)
    run_gemm(s, acc, g_hwh + (size_t)m0 * 256, g_hwl + (size_t)m0 * 256, 256,
             g_f8h + (size_t)b * 256 * BNP, 256, tid, lane, wm, wn);
    run_gemm(s, acc, g_uwh + (size_t)m0 * 128, g_uwl + (size_t)m0 * 128, 128,
             g_ph + (size_t)b * 128 * BNP, 128, tid, lane, wm, wn);

    // ---- write S (hi plane) ----
#pragma unroll
    for (int mt = 0; mt < 2; mt++)
#pragma unroll
    for (int half = 0; half < 2; half++) {
        int row = m0 + wm * 32 + mt * 16 + lr + half * 8;
        if (row >= NTOK) continue;
        float bv = h_b[row] + u_b[row];
        size_t ro = (size_t)(b * 192 + row) * BNP;
#pragma unroll
        for (int t = 0; t < 6; t++)
#pragma unroll
            for (int e = 0; e < 2; e++) {
                int n = wn * 48 + t * 8 + lc + e;
                if (n < NTOK)
                    g_Sh[ro + n] = __float2half_rn(acc[mt][t][half * 2 + e] + bv);
            }
    }
}

// ============================================================
// out = gamma * (c_w @ S + c_b) + x     grid (8, BATCH), K = 192
// ============================================================
__global__ __launch_bounds__(256, 2) void out_kernel(const float* __restrict__ c_b,
                                                     const float* __restrict__ x,
                                                     const float* __restrict__ gamma_p,
                                                     float* __restrict__ Out)
{
    extern __shared__ char smem_raw[];
    Smem& s = *reinterpret_cast<Smem*>(smem_raw);
    int b   = blockIdx.y;
    int m0  = blockIdx.x * 64;
    int tid = threadIdx.x, lane = tid & 31, wid = tid >> 5;
    int wm = wid & 1, wn = wid >> 1;
    int lr = lane >> 2, lc = (lane & 3) * 2;

    float acc[2][6][4] = {};
    run_gemm(s, acc, g_cwh + (size_t)m0 * 192, g_cwl + (size_t)m0 * 192, 192,
             g_Sh + (size_t)b * 192 * BNP, 192, tid, lane, wm, wn);

    float gma = *gamma_p;
#pragma unroll
    for (int mt = 0; mt < 2; mt++)
#pragma unroll
    for (int half = 0; half < 2; half++) {
        int m = m0 + wm * 32 + mt * 16 + lr + half * 8;
        float bv = c_b[m];
        const float* xrow = x + (size_t)b * 512 * NTOK + (size_t)m * NTOK;
        float* orow = Out + (size_t)b * 512 * NTOK + (size_t)m * NTOK;
#pragma unroll
        for (int t = 0; t < 6; t++)
#pragma unroll
            for (int e = 0; e < 2; e++) {
                int n = wn * 48 + t * 8 + lc + e;
                if (n < NTOK)
                    orow[n] = fmaf(gma, acc[mt][t][half * 2 + e] + bv, xrow[n]);
            }
    }
}

// ============================================================
extern "C" void kernel_launch(void* const* d_in, const int* in_sizes, int n_in,
                              void* d_out, int out_size)
{
    const float* x    = (const float*)d_in[0];
    const float* f5   = (const float*)d_in[1];
    const float* f8   = (const float*)d_in[2];
    const float* f_w  = (const float*)d_in[3];
    const float* f_b  = (const float*)d_in[4];
    const float* g_w  = (const float*)d_in[5];
    const float* g_b  = (const float*)d_in[6];
    const float* h_w  = (const float*)d_in[7];
    const float* h_b  = (const float*)d_in[8];
    const float* u_w  = (const float*)d_in[9];
    const float* u_b  = (const float*)d_in[10];
    const float* c_w  = (const float*)d_in[11];
    const float* c_b  = (const float*)d_in[12];
    const float* gma  = (const float*)d_in[13];

    float* out = (float*)d_out;

    cudaFuncSetAttribute(fg_kernel,  cudaFuncAttributeMaxDynamicSharedMemorySize, (int)SMEM_BYTES);
    cudaFuncSetAttribute(s_kernel,   cudaFuncAttributeMaxDynamicSharedMemorySize, (int)SMEM_BYTES);
    cudaFuncSetAttribute(out_kernel, cudaFuncAttributeMaxDynamicSharedMemorySize, (int)SMEM_BYTES);

    int wtot = 2 * 64 * 512 + 169 * 256 + 169 * 128 + 512 * 169;
    split_w_kernel<<<(wtot + 255) / 256, 256>>>(f_w, g_w, h_w, u_w, c_w);
    split_x_kernel<<<(XE + FE + 255) / 256, 256>>>(x, f8);
    {
        int total = BATCH * 128 * NTOK;
        pool_kernel<<<(total + 255) / 256, 256>>>(f5);
    }
    fg_kernel<<<dim3(2, BATCH), 256, SMEM_BYTES>>>(f_b, g_b);
    s_kernel<<<dim3(3, BATCH), 256, SMEM_BYTES>>>(h_b, u_b);
    out_kernel<<<dim3(8, BATCH), 256, SMEM_BYTES>>>(c_b, x, gma, out);
}

// round 14
// speedup vs baseline: 1.2900x; 1.0900x over previous
#include <cuda_runtime.h>
#include <cuda_fp16.h>
#include <math_constants.h>
#include <cstdint>

#define HW 13
#define NTOK 169
#define BNP 192          // fp16 B-operand column stride
#define BATCH 256

typedef __half hf;

// ---- B-operand planes: [k][BNP] fp16 ----
__device__ __align__(16) hf g_xh [BATCH * 512 * BNP];
__device__ __align__(16) hf g_f8h[BATCH * 256 * BNP];
__device__ __align__(16) hf g_ph [BATCH * 128 * BNP];
__device__ __align__(16) hf g_Gh [BATCH * 64 * BNP];
__device__ __align__(16) hf g_Sh [BATCH * 192 * BNP];   // rows 169+ stay 0
// ---- A-operand planes: [m][K] fp16 ----
__device__ __align__(16) hf g_fwh[64 * 512];
__device__ __align__(16) hf g_gwh[64 * 512];
__device__ __align__(16) hf g_hwh[192 * 256];
__device__ __align__(16) hf g_uwh[192 * 128];
__device__ __align__(16) hf g_cwh[512 * 192];           // cols 176+ stay 0
__device__ __align__(16) hf g_Fh [BATCH * 192 * 64];

// ============================================================
// low-level helpers
// ============================================================
__device__ __forceinline__ unsigned smem_u32(const void* p) {
    return (unsigned)__cvta_generic_to_shared(p);
}
__device__ __forceinline__ void cpa16(void* dst, const void* src) {
    asm volatile("cp.async.cg.shared.global [%0], [%1], 16;"
                 :: "r"(smem_u32(dst)), "l"(src));
}
#define CP_COMMIT()  asm volatile("cp.async.commit_group;")
#define CP_WAIT1()   asm volatile("cp.async.wait_group 1;")
#define CP_WAIT0()   asm volatile("cp.async.wait_group 0;")

__device__ __forceinline__ void ldsm_x4(unsigned (&r)[4], unsigned a) {
    asm volatile("ldmatrix.sync.aligned.m8n8.x4.shared.b16 {%0,%1,%2,%3}, [%4];"
        : "=r"(r[0]), "=r"(r[1]), "=r"(r[2]), "=r"(r[3]) : "r"(a));
}
__device__ __forceinline__ void ldsm_x4t(unsigned (&r)[4], unsigned a) {
    asm volatile("ldmatrix.sync.aligned.m8n8.x4.trans.shared.b16 {%0,%1,%2,%3}, [%4];"
        : "=r"(r[0]), "=r"(r[1]), "=r"(r[2]), "=r"(r[3]) : "r"(a));
}
__device__ __forceinline__ void mma16816(float (&d)[4], const unsigned (&a)[4],
                                         unsigned b0, unsigned b1) {
    asm volatile("mma.sync.aligned.m16n8k16.row.col.f32.f16.f16.f32 "
        "{%0,%1,%2,%3}, {%4,%5,%6,%7}, {%8,%9}, {%0,%1,%2,%3};"
        : "+f"(d[0]), "+f"(d[1]), "+f"(d[2]), "+f"(d[3])
        : "r"(a[0]), "r"(a[1]), "r"(a[2]), "r"(a[3]), "r"(b0), "r"(b1));
}

// ============================================================
// GEMM: CTA tile 64M x 192N, warp grid 2M x 4N (32M x 48N per warp).
// Pure fp16: per k16/warp 5 LDSM, 12 HMMA.
// ============================================================
struct Smem {
    hf Ah[2][64][40];     // 10240 B
    hf Bh[2][32][200];    // 25600 B
};                         // 35840 B total
#define SMEM_BYTES sizeof(Smem)

__device__ __forceinline__ void fill(Smem& s, int buf,
                                     const hf* __restrict__ Ah, int lda,
                                     const hf* __restrict__ Bh,
                                     int k0, int tid)
{
#pragma unroll
    for (int i = 0; i < 4; i++) {       // 256 A-units + 768 B-units = 1024 16B ops
        int idx = tid + i * 256;
        if (idx < 256) {
            int r = idx >> 2, q = idx & 3;
            cpa16(&s.Ah[buf][r][q * 8], Ah + (size_t)r * lda + k0 + q * 8);
        } else {
            int j = idx - 256;
            int rr = j / 24, q = j - rr * 24;
            cpa16(&s.Bh[buf][rr][q * 8], Bh + (size_t)(k0 + rr) * BNP + q * 8);
        }
    }
}

__device__ __forceinline__ void mma_chunk(float (&acc)[2][6][4], Smem& s, int buf,
                                          int lane, int wm, int wn)
{
    unsigned rsel = lane & 15;
    unsigned csel = (lane >> 4) << 3;
#pragma unroll
    for (int ks = 0; ks < 32; ks += 16) {
        unsigned ah[2][4];
#pragma unroll
        for (int mt = 0; mt < 2; mt++)
            ldsm_x4(ah[mt], smem_u32(&s.Ah[buf][wm * 32 + mt * 16 + rsel][ks + csel]));
#pragma unroll
        for (int g = 0; g < 3; g++) {
            unsigned bh[4];
            ldsm_x4t(bh, smem_u32(&s.Bh[buf][ks + rsel][wn * 48 + g * 16 + csel]));
#pragma unroll
            for (int mt = 0; mt < 2; mt++) {
                mma16816(acc[mt][2 * g],     ah[mt], bh[0], bh[1]);
                mma16816(acc[mt][2 * g + 1], ah[mt], bh[2], bh[3]);
            }
        }
    }
}

__device__ __forceinline__ void run_gemm(Smem& s, float (&acc)[2][6][4],
                                         const hf* __restrict__ Ah, int lda,
                                         const hf* __restrict__ Bh,
                                         int K, int tid, int lane, int wm, int wn)
{
    int nt = K >> 5;
    fill(s, 0, Ah, lda, Bh, 0, tid);
    CP_COMMIT();
    for (int t = 0; t < nt; t++) {
        if (t + 1 < nt) {
            fill(s, (t + 1) & 1, Ah, lda, Bh, (t + 1) * 32, tid);
            CP_COMMIT();
            CP_WAIT1();
        } else {
            CP_WAIT0();
        }
        __syncthreads();
        mma_chunk(acc, s, t & 1, lane, wm, wn);
        __syncthreads();
    }
}

// ============================================================
// split / repack kernels
// ============================================================
__global__ __launch_bounds__(256) void split_w_kernel(
    const float* __restrict__ f_w, const float* __restrict__ g_w,
    const float* __restrict__ h_w, const float* __restrict__ u_w,
    const float* __restrict__ c_w)
{
    int idx = blockIdx.x * 256 + threadIdx.x;
    float v; hf* dh;
    if (idx < 64 * 512) {
        v = f_w[idx]; dh = g_fwh + idx;
    } else if ((idx -= 64 * 512) < 64 * 512) {
        v = g_w[idx]; dh = g_gwh + idx;
    } else if ((idx -= 64 * 512) < 169 * 256) {
        v = h_w[idx]; dh = g_hwh + idx;
    } else if ((idx -= 169 * 256) < 169 * 128) {
        v = u_w[idx]; dh = g_uwh + idx;
    } else if ((idx -= 169 * 128) < 512 * 169) {
        int m = idx / 169, k = idx - m * 169;
        v = c_w[idx];
        dh = g_cwh + (size_t)m * 192 + k;
    } else return;
    *dh = __float2half_rn(v);
}

#define XE (BATCH * 512 * NTOK)
#define FE (BATCH * 256 * NTOK)
__global__ __launch_bounds__(256) void split_x_kernel(const float* __restrict__ x,
                                                      const float* __restrict__ f8)
{
    int idx = blockIdx.x * 256 + threadIdx.x;
    const float* src; hf* bh;
    if (idx < XE)              { src = x;  bh = g_xh; }
    else if ((idx -= XE) < FE) { src = f8; bh = g_f8h; }
    else return;
    int row = idx / NTOK, n = idx - row * NTOK;
    bh[(size_t)row * BNP + n] = __float2half_rn(src[idx]);
}

// ============================================================
// antialiased bilinear 26 -> 13 (jax antialias=True)
// ============================================================
__constant__ int   c_tap0[HW] = { 0, 1, 3, 5, 7, 9,11,13,15,17,19,21,23};
__constant__ float c_wt[HW][4] = {
    {3.f/7.f, 3.f/7.f, 1.f/7.f, 0.f},
    {0.125f, 0.375f, 0.375f, 0.125f}, {0.125f, 0.375f, 0.375f, 0.125f},
    {0.125f, 0.375f, 0.375f, 0.125f}, {0.125f, 0.375f, 0.375f, 0.125f},
    {0.125f, 0.375f, 0.375f, 0.125f}, {0.125f, 0.375f, 0.375f, 0.125f},
    {0.125f, 0.375f, 0.375f, 0.125f}, {0.125f, 0.375f, 0.375f, 0.125f},
    {0.125f, 0.375f, 0.375f, 0.125f}, {0.125f, 0.375f, 0.375f, 0.125f},
    {0.125f, 0.375f, 0.375f, 0.125f},
    {1.f/7.f, 3.f/7.f, 3.f/7.f, 0.f}
};

__global__ __launch_bounds__(256) void pool_kernel(const float* __restrict__ f5) {
    int idx = blockIdx.x * blockDim.x + threadIdx.x;
    if (idx >= BATCH * 128 * NTOK) return;
    int n  = idx % NTOK;
    int bc = idx / NTOK;
    int j = n % HW, i = n / HW;
    const float* src = f5 + (size_t)bc * 26 * 26;
    int r0 = c_tap0[i], cc0 = c_tap0[j];
    float acc = 0.f;
#pragma unroll
    for (int ri = 0; ri < 4; ri++) {
        float wr = c_wt[i][ri];
        if (wr == 0.f) continue;
        int r = r0 + ri;
        float rowv = 0.f;
#pragma unroll
        for (int ci = 0; ci < 4; ci++) {
            float wc = c_wt[j][ci];
            if (wc == 0.f) continue;
            rowv = fmaf(wc, src[r * 26 + cc0 + ci], rowv);
        }
        acc = fmaf(wr, rowv, acc);
    }
    g_ph[(size_t)bc * BNP + n] = __float2half_rn(acc);
}

// ============================================================
// F / G projections: grid (2, BATCH)
// ============================================================
__global__ __launch_bounds__(256, 3) void fg_kernel(const float* __restrict__ f_b,
                                                    const float* __restrict__ g_b)
{
    extern __shared__ char smem_raw[];
    Smem& s = *reinterpret_cast<Smem*>(smem_raw);
    int b    = blockIdx.y;
    bool isG = blockIdx.x != 0;
    int tid = threadIdx.x, lane = tid & 31, wid = tid >> 5;
    int wm = wid & 1, wn = wid >> 1;

    float acc[2][6][4] = {};
    run_gemm(s, acc, isG ? g_gwh : g_fwh, 512,
             g_xh + (size_t)b * 512 * BNP, 512, tid, lane, wm, wn);

    const float* bias = isG ? g_b : f_b;
    int lr = lane >> 2, lc = (lane & 3) * 2;
#pragma unroll
    for (int mt = 0; mt < 2; mt++)
#pragma unroll
    for (int half = 0; half < 2; half++) {
        int m = wm * 32 + mt * 16 + lr + half * 8;
        float bv = bias[m];
#pragma unroll
        for (int t = 0; t < 6; t++) {
#pragma unroll
            for (int e = 0; e < 2; e++) {
                int n = wn * 48 + t * 8 + lc + e;
                if (n >= NTOK) continue;
                float v = acc[mt][t][half * 2 + e] + bv;
                if (isG)
                    g_Gh[(size_t)(b * 64 + m) * BNP + n] = __float2half_rn(v);
                else
                    g_Fh[(size_t)(b * 192 + n) * 64 + m] = __float2half_rn(v);
            }
        }
    }
}

// ============================================================
// S = softmax(F^T G) + h_w@f8 + u_w@pool + bias     grid (3, BATCH)
// ============================================================
__global__ __launch_bounds__(256, 3) void s_kernel(const float* __restrict__ h_b,
                                                   const float* __restrict__ u_b)
{
    extern __shared__ char smem_raw[];
    Smem& s = *reinterpret_cast<Smem*>(smem_raw);
    __shared__ float redM[4][64], redS[4][64];
    int b   = blockIdx.y;
    int m0  = blockIdx.x * 64;
    int tid = threadIdx.x, lane = tid & 31, wid = tid >> 5;
    int wm = wid & 1, wn = wid >> 1;
    int lr = lane >> 2, lc = (lane & 3) * 2;

    float acc[2][6][4] = {};

    // energy = F^T G  (K = 64)
    run_gemm(s, acc, g_Fh + (size_t)(b * 192 + m0) * 64, 64,
             g_Gh + (size_t)b * 64 * BNP, 64, tid, lane, wm, wn);

    // ---- softmax over cols ----
    float pmax[2][2];
#pragma unroll
    for (int mt = 0; mt < 2; mt++)
#pragma unroll
        for (int half = 0; half < 2; half++) {
            float m = -CUDART_INF_F;
#pragma unroll
            for (int t = 0; t < 6; t++)
#pragma unroll
                for (int e = 0; e < 2; e++) {
                    int n = wn * 48 + t * 8 + lc + e;
                    if (n < NTOK) m = fmaxf(m, acc[mt][t][half * 2 + e]);
                }
            pmax[mt][half] = m;
        }
#pragma unroll
    for (int off = 1; off < 4; off <<= 1)
#pragma unroll
        for (int mt = 0; mt < 2; mt++)
#pragma unroll
            for (int half = 0; half < 2; half++)
                pmax[mt][half] = fmaxf(pmax[mt][half],
                    __shfl_xor_sync(0xffffffffu, pmax[mt][half], off, 4));
    if ((lane & 3) == 0) {
#pragma unroll
        for (int mt = 0; mt < 2; mt++)
#pragma unroll
            for (int half = 0; half < 2; half++)
                redM[wn][wm * 32 + mt * 16 + lr + half * 8] = pmax[mt][half];
    }
    __syncthreads();
    float mx[2][2];
#pragma unroll
    for (int mt = 0; mt < 2; mt++)
#pragma unroll
        for (int half = 0; half < 2; half++) {
            int row = wm * 32 + mt * 16 + lr + half * 8;
            mx[mt][half] = fmaxf(fmaxf(redM[0][row], redM[1][row]),
                                 fmaxf(redM[2][row], redM[3][row]));
        }
    float psum[2][2] = {};
#pragma unroll
    for (int mt = 0; mt < 2; mt++)
#pragma unroll
        for (int half = 0; half < 2; half++)
#pragma unroll
            for (int t = 0; t < 6; t++)
#pragma unroll
                for (int e = 0; e < 2; e++) {
                    int n = wn * 48 + t * 8 + lc + e;
                    float ev = (n < NTOK) ?
                        __expf(acc[mt][t][half * 2 + e] - mx[mt][half]) : 0.f;
                    acc[mt][t][half * 2 + e] = ev;
                    psum[mt][half] += ev;
                }
#pragma unroll
    for (int off = 1; off < 4; off <<= 1)
#pragma unroll
        for (int mt = 0; mt < 2; mt++)
#pragma unroll
            for (int half = 0; half < 2; half++)
                psum[mt][half] += __shfl_xor_sync(0xffffffffu, psum[mt][half], off, 4);
    if ((lane & 3) == 0) {
#pragma unroll
        for (int mt = 0; mt < 2; mt++)
#pragma unroll
            for (int half = 0; half < 2; half++)
                redS[wn][wm * 32 + mt * 16 + lr + half * 8] = psum[mt][half];
    }
    __syncthreads();
#pragma unroll
    for (int mt = 0; mt < 2; mt++)
#pragma unroll
        for (int half = 0; half < 2; half++) {
            int row = wm * 32 + mt * 16 + lr + half * 8;
            float inv = 1.f / (redS[0][row] + redS[1][row] + redS[2][row] + redS[3][row]);
#pragma unroll
            for (int t = 0; t < 6; t++)
#pragma unroll
                for (int e = 0; e < 2; e++)
                    acc[mt][t][half * 2 + e] *= inv;
        }
    __syncthreads();

    // += h_w @ f8 (K=256), += u_w @ pool (K=128)
    run_gemm(s, acc, g_hwh + (size_t)m0 * 256, 256,
             g_f8h + (size_t)b * 256 * BNP, 256, tid, lane, wm, wn);
    run_gemm(s, acc, g_uwh + (size_t)m0 * 128, 128,
             g_ph + (size_t)b * 128 * BNP, 128, tid, lane, wm, wn);

    // ---- write S ----
#pragma unroll
    for (int mt = 0; mt < 2; mt++)
#pragma unroll
    for (int half = 0; half < 2; half++) {
        int row = m0 + wm * 32 + mt * 16 + lr + half * 8;
        if (row >= NTOK) continue;
        float bv = h_b[row] + u_b[row];
        size_t ro = (size_t)(b * 192 + row) * BNP;
#pragma unroll
        for (int t = 0; t < 6; t++)
#pragma unroll
            for (int e = 0; e < 2; e++) {
                int n = wn * 48 + t * 8 + lc + e;
                if (n < NTOK)
                    g_Sh[ro + n] = __float2half_rn(acc[mt][t][half * 2 + e] + bv);
            }
    }
}

// ============================================================
// out = gamma * (c_w @ S + c_b) + x     grid (8, BATCH), K = 192
// ============================================================
__global__ __launch_bounds__(256, 3) void out_kernel(const float* __restrict__ c_b,
                                                     const float* __restrict__ x,
                                                     const float* __restrict__ gamma_p,
                                                     float* __restrict__ Out)
{
    extern __shared__ char smem_raw[];
    Smem& s = *reinterpret_cast<Smem*>(smem_raw);
    int b   = blockIdx.y;
    int m0  = blockIdx.x * 64;
    int tid = threadIdx.x, lane = tid & 31, wid = tid >> 5;
    int wm = wid & 1, wn = wid >> 1;
    int lr = lane >> 2, lc = (lane & 3) * 2;

    float acc[2][6][4] = {};
    run_gemm(s, acc, g_cwh + (size_t)m0 * 192, 192,
             g_Sh + (size_t)b * 192 * BNP, 192, tid, lane, wm, wn);

    float gma = *gamma_p;
#pragma unroll
    for (int mt = 0; mt < 2; mt++)
#pragma unroll
    for (int half = 0; half < 2; half++) {
        int m = m0 + wm * 32 + mt * 16 + lr + half * 8;
        float bv = c_b[m];
        const float* xrow = x + (size_t)b * 512 * NTOK + (size_t)m * NTOK;
        float* orow = Out + (size_t)b * 512 * NTOK + (size_t)m * NTOK;
#pragma unroll
        for (int t = 0; t < 6; t++)
#pragma unroll
            for (int e = 0; e < 2; e++) {
                int n = wn * 48 + t * 8 + lc + e;
                if (n < NTOK)
                    orow[n] = fmaf(gma, acc[mt][t][half * 2 + e] + bv, xrow[n]);
            }
    }
}

// ============================================================
extern "C" void kernel_launch(void* const* d_in, const int* in_sizes, int n_in,
                              void* d_out, int out_size)
{
    const float* x    = (const float*)d_in[0];
    const float* f5   = (const float*)d_in[1];
    const float* f8   = (const float*)d_in[2];
    const float* f_w  = (const float*)d_in[3];
    const float* f_b  = (const float*)d_in[4];
    const float* g_w  = (const float*)d_in[5];
    const float* g_b  = (const float*)d_in[6];
    const float* h_w  = (const float*)d_in[7];
    const float* h_b  = (const float*)d_in[8];
    const float* u_w  = (const float*)d_in[9];
    const float* u_b  = (const float*)d_in[10];
    const float* c_w  = (const float*)d_in[11];
    const float* c_b  = (const float*)d_in[12];
    const float* gma  = (const float*)d_in[13];

    float* out = (float*)d_out;

    cudaFuncSetAttribute(fg_kernel,  cudaFuncAttributeMaxDynamicSharedMemorySize, (int)SMEM_BYTES);
    cudaFuncSetAttribute(s_kernel,   cudaFuncAttributeMaxDynamicSharedMemorySize, (int)SMEM_BYTES);
    cudaFuncSetAttribute(out_kernel, cudaFuncAttributeMaxDynamicSharedMemorySize, (int)SMEM_BYTES);

    int wtot = 2 * 64 * 512 + 169 * 256 + 169 * 128 + 512 * 169;
    split_w_kernel<<<(wtot + 255) / 256, 256>>>(f_w, g_w, h_w, u_w, c_w);
    split_x_kernel<<<(XE + FE + 255) / 256, 256>>>(x, f8);
    {
        int total = BATCH * 128 * NTOK;
        pool_kernel<<<(total + 255) / 256, 256>>>(f5);
    }
    fg_kernel<<<dim3(2, BATCH), 256, SMEM_BYTES>>>(f_b, g_b);
    s_kernel<<<dim3(3, BATCH), 256, SMEM_BYTES>>>(h_b, u_b);
    out_kernel<<<dim3(8, BATCH), 256, SMEM_BYTES>>>(c_b, x, gma, out);
}

// round 15
// speedup vs baseline: 1.3665x; 1.0593x over previous
#include <cuda_runtime.h>
#include <cuda_fp16.h>
#include <math_constants.h>
#include <cstdint>

#define HW 13
#define NTOK 169
#define BNP 192          // fp16 B-operand column stride
#define BATCH 256

typedef __half hf;

// ---- B-operand planes: [k][BNP] fp16 ----
__device__ __align__(16) hf g_xh [BATCH * 512 * BNP];
__device__ __align__(16) hf g_f8h[BATCH * 256 * BNP];
__device__ __align__(16) hf g_ph [BATCH * 128 * BNP];
__device__ __align__(16) hf g_Gh [BATCH * 64 * BNP];
__device__ __align__(16) hf g_Sh [BATCH * 192 * BNP];   // rows 169+ stay 0
// ---- A-operand planes: [m][K] fp16 ----
__device__ __align__(16) hf g_fwh[64 * 512];
__device__ __align__(16) hf g_gwh[64 * 512];
__device__ __align__(16) hf g_hwh[192 * 256];
__device__ __align__(16) hf g_uwh[192 * 128];
__device__ __align__(16) hf g_cwh[512 * 192];           // cols 176+ stay 0
__device__ __align__(16) hf g_Fh [BATCH * 192 * 64];

// ============================================================
// low-level helpers
// ============================================================
__device__ __forceinline__ unsigned smem_u32(const void* p) {
    return (unsigned)__cvta_generic_to_shared(p);
}
__device__ __forceinline__ void cpa16(void* dst, const void* src) {
    asm volatile("cp.async.cg.shared.global [%0], [%1], 16;"
                 :: "r"(smem_u32(dst)), "l"(src));
}
#define CP_COMMIT()  asm volatile("cp.async.commit_group;")
#define CP_WAIT0()   asm volatile("cp.async.wait_group 0;")

__device__ __forceinline__ void ldsm_x4(unsigned (&r)[4], unsigned a) {
    asm volatile("ldmatrix.sync.aligned.m8n8.x4.shared.b16 {%0,%1,%2,%3}, [%4];"
        : "=r"(r[0]), "=r"(r[1]), "=r"(r[2]), "=r"(r[3]) : "r"(a));
}
__device__ __forceinline__ void ldsm_x4t(unsigned (&r)[4], unsigned a) {
    asm volatile("ldmatrix.sync.aligned.m8n8.x4.trans.shared.b16 {%0,%1,%2,%3}, [%4];"
        : "=r"(r[0]), "=r"(r[1]), "=r"(r[2]), "=r"(r[3]) : "r"(a));
}
__device__ __forceinline__ void mma16816(float (&d)[4], const unsigned (&a)[4],
                                         unsigned b0, unsigned b1) {
    asm volatile("mma.sync.aligned.m16n8k16.row.col.f32.f16.f16.f32 "
        "{%0,%1,%2,%3}, {%4,%5,%6,%7}, {%8,%9}, {%0,%1,%2,%3};"
        : "+f"(d[0]), "+f"(d[1]), "+f"(d[2]), "+f"(d[3])
        : "r"(a[0]), "r"(a[1]), "r"(a[2]), "r"(a[3]), "r"(b0), "r"(b1));
}

// ============================================================
// GEMM: CTA tile 64M x 192N, warp grid 2M x 4N (32M x 48N per warp).
// Pure fp16: per k16/warp 5 LDSM, 12 HMMA. Single-sync double buffer.
// ============================================================
struct Smem {
    hf Ah[2][64][40];     // 10240 B
    hf Bh[2][32][200];    // 25600 B
};                         // 35840 B total
#define SMEM_BYTES sizeof(Smem)

__device__ __forceinline__ void fill(Smem& s, int buf,
                                     const hf* __restrict__ Ah, int lda,
                                     const hf* __restrict__ Bh,
                                     int k0, int tid)
{
#pragma unroll
    for (int i = 0; i < 4; i++) {       // 256 A-units + 768 B-units = 1024 16B ops
        int idx = tid + i * 256;
        if (idx < 256) {
            int r = idx >> 2, q = idx & 3;
            cpa16(&s.Ah[buf][r][q * 8], Ah + (size_t)r * lda + k0 + q * 8);
        } else {
            int j = idx - 256;
            int rr = j / 24, q = j - rr * 24;
            cpa16(&s.Bh[buf][rr][q * 8], Bh + (size_t)(k0 + rr) * BNP + q * 8);
        }
    }
}

__device__ __forceinline__ void mma_chunk(float (&acc)[2][6][4], Smem& s, int buf,
                                          int lane, int wm, int wn)
{
    unsigned rsel = lane & 15;
    unsigned csel = (lane >> 4) << 3;
#pragma unroll
    for (int ks = 0; ks < 32; ks += 16) {
        unsigned ah[2][4];
#pragma unroll
        for (int mt = 0; mt < 2; mt++)
            ldsm_x4(ah[mt], smem_u32(&s.Ah[buf][wm * 32 + mt * 16 + rsel][ks + csel]));
#pragma unroll
        for (int g = 0; g < 3; g++) {
            unsigned bh[4];
            ldsm_x4t(bh, smem_u32(&s.Bh[buf][ks + rsel][wn * 48 + g * 16 + csel]));
#pragma unroll
            for (int mt = 0; mt < 2; mt++) {
                mma16816(acc[mt][2 * g],     ah[mt], bh[0], bh[1]);
                mma16816(acc[mt][2 * g + 1], ah[mt], bh[2], bh[3]);
            }
        }
    }
}

// single-sync pipeline: wait(fill t) -> barrier -> issue fill(t+1) -> mma(t)
__device__ __forceinline__ void run_gemm(Smem& s, float (&acc)[2][6][4],
                                         const hf* __restrict__ Ah, int lda,
                                         const hf* __restrict__ Bh,
                                         int K, int tid, int lane, int wm, int wn)
{
    int nt = K >> 5;
    fill(s, 0, Ah, lda, Bh, 0, tid);
    CP_COMMIT();
    for (int t = 0; t < nt; t++) {
        CP_WAIT0();
        __syncthreads();
        if (t + 1 < nt) {
            fill(s, (t + 1) & 1, Ah, lda, Bh, (t + 1) << 5, tid);
            CP_COMMIT();
        }
        mma_chunk(acc, s, t & 1, lane, wm, wn);
    }
    __syncthreads();
}

// two back-to-back GEMMs through one pipeline (no drain between)
struct Seg { const hf* A; int lda; const hf* B; int K; };

__device__ __forceinline__ void run_gemm_seg2(Smem& s, float (&acc)[2][6][4],
                                              Seg s0, Seg s1,
                                              int tid, int lane, int wm, int wn)
{
    int nt0 = s0.K >> 5, nt1 = s1.K >> 5, nt = nt0 + nt1;
    auto fillc = [&](int buf, int c) {
        if (c < nt0) fill(s, buf, s0.A, s0.lda, s0.B, c << 5, tid);
        else         fill(s, buf, s1.A, s1.lda, s1.B, (c - nt0) << 5, tid);
    };
    fillc(0, 0);
    CP_COMMIT();
    for (int t = 0; t < nt; t++) {
        CP_WAIT0();
        __syncthreads();
        if (t + 1 < nt) { fillc((t + 1) & 1, t + 1); CP_COMMIT(); }
        mma_chunk(acc, s, t & 1, lane, wm, wn);
    }
    __syncthreads();
}

// ============================================================
// fused prepare: weights (scalar) + x/f8 (2-col vectorized) + pool
// ============================================================
__constant__ int   c_tap0[HW] = { 0, 1, 3, 5, 7, 9,11,13,15,17,19,21,23};
__constant__ float c_wt[HW][4] = {
    {3.f/7.f, 3.f/7.f, 1.f/7.f, 0.f},
    {0.125f, 0.375f, 0.375f, 0.125f}, {0.125f, 0.375f, 0.375f, 0.125f},
    {0.125f, 0.375f, 0.375f, 0.125f}, {0.125f, 0.375f, 0.375f, 0.125f},
    {0.125f, 0.375f, 0.375f, 0.125f}, {0.125f, 0.375f, 0.375f, 0.125f},
    {0.125f, 0.375f, 0.375f, 0.125f}, {0.125f, 0.375f, 0.375f, 0.125f},
    {0.125f, 0.375f, 0.375f, 0.125f}, {0.125f, 0.375f, 0.375f, 0.125f},
    {0.125f, 0.375f, 0.375f, 0.125f},
    {1.f/7.f, 3.f/7.f, 3.f/7.f, 0.f}
};

#define NW1 (64 * 512)
#define NW2 (64 * 512)
#define NW3 (169 * 256)
#define NW4 (169 * 128)
#define NW5 (512 * 169)
#define WTOT (NW1 + NW2 + NW3 + NW4 + NW5)
#define XROWS (BATCH * 512)
#define FROWS (BATCH * 256)
#define XF2  ((XROWS + FROWS) * 85)       // 2-col units per row
#define PTOT (BATCH * 128 * NTOK)

__global__ __launch_bounds__(256) void prepare_kernel(
    const float* __restrict__ f_w, const float* __restrict__ g_w,
    const float* __restrict__ h_w, const float* __restrict__ u_w,
    const float* __restrict__ c_w,
    const float* __restrict__ x,  const float* __restrict__ f8,
    const float* __restrict__ f5)
{
    int idx = blockIdx.x * 256 + threadIdx.x;
    if (idx < WTOT) {                       // ---- weights (scalar) ----
        float v; hf* dh;
        if (idx < NW1) { v = f_w[idx]; dh = g_fwh + idx; }
        else if ((idx -= NW1) < NW2) { v = g_w[idx]; dh = g_gwh + idx; }
        else if ((idx -= NW2) < NW3) { v = h_w[idx]; dh = g_hwh + idx; }
        else if ((idx -= NW3) < NW4) { v = u_w[idx]; dh = g_uwh + idx; }
        else {
            idx -= NW4;
            int m = idx / 169, k = idx - m * 169;
            v = c_w[idx]; dh = g_cwh + (size_t)m * 192 + k;
        }
        *dh = __float2half_rn(v);
        return;
    }
    idx -= WTOT;
    if (idx < XF2) {                        // ---- x / f8 convert (2 cols) ----
        int row = idx / 85, q = idx - row * 85;
        int n = 2 * q;
        const float* src; hf* bh;
        if (row < XROWS) { src = x;  bh = g_xh; }
        else { row -= XROWS; src = f8; bh = g_f8h; }
        const float* sr = src + (size_t)row * NTOK;
        hf* dr = bh + (size_t)row * BNP;
        if (n + 1 < NTOK) {
            __half2 h2 = __floats2half2_rn(sr[n], sr[n + 1]);
            *(__half2*)&dr[n] = h2;
        } else if (n < NTOK) {
            dr[n] = __float2half_rn(sr[n]);
        }
        return;
    }
    idx -= XF2;
    if (idx < PTOT) {                       // ---- antialiased pool 26->13 ----
        int n  = idx % NTOK;
        int bc = idx / NTOK;
        int j = n % HW, i = n / HW;
        const float* src = f5 + (size_t)bc * 26 * 26;
        int r0 = c_tap0[i], cc0 = c_tap0[j];
        float acc = 0.f;
#pragma unroll
        for (int ri = 0; ri < 4; ri++) {
            float wr = c_wt[i][ri];
            if (wr == 0.f) continue;
            int r = r0 + ri;
            float rowv = 0.f;
#pragma unroll
            for (int ci = 0; ci < 4; ci++) {
                float wc = c_wt[j][ci];
                if (wc == 0.f) continue;
                rowv = fmaf(wc, src[r * 26 + cc0 + ci], rowv);
            }
            acc = fmaf(wr, rowv, acc);
        }
        g_ph[(size_t)bc * BNP + n] = __float2half_rn(acc);
    }
}

// ============================================================
// F / G projections: grid (2, BATCH)
// ============================================================
__global__ __launch_bounds__(256, 3) void fg_kernel(const float* __restrict__ f_b,
                                                    const float* __restrict__ g_b)
{
    extern __shared__ char smem_raw[];
    Smem& s = *reinterpret_cast<Smem*>(smem_raw);
    int b    = blockIdx.y;
    bool isG = blockIdx.x != 0;
    int tid = threadIdx.x, lane = tid & 31, wid = tid >> 5;
    int wm = wid & 1, wn = wid >> 1;

    float acc[2][6][4] = {};
    run_gemm(s, acc, isG ? g_gwh : g_fwh, 512,
             g_xh + (size_t)b * 512 * BNP, 512, tid, lane, wm, wn);

    const float* bias = isG ? g_b : f_b;
    int lr = lane >> 2, lc = (lane & 3) * 2;
#pragma unroll
    for (int mt = 0; mt < 2; mt++)
#pragma unroll
    for (int half = 0; half < 2; half++) {
        int m = wm * 32 + mt * 16 + lr + half * 8;
        float bv = bias[m];
#pragma unroll
        for (int t = 0; t < 6; t++) {
#pragma unroll
            for (int e = 0; e < 2; e++) {
                int n = wn * 48 + t * 8 + lc + e;
                if (n >= NTOK) continue;
                float v = acc[mt][t][half * 2 + e] + bv;
                if (isG)
                    g_Gh[(size_t)(b * 64 + m) * BNP + n] = __float2half_rn(v);
                else
                    g_Fh[(size_t)(b * 192 + n) * 64 + m] = __float2half_rn(v);
            }
        }
    }
}

// ============================================================
// S = softmax(F^T G) + h_w@f8 + u_w@pool + bias     grid (3, BATCH)
// ============================================================
__global__ __launch_bounds__(256, 3) void s_kernel(const float* __restrict__ h_b,
                                                   const float* __restrict__ u_b)
{
    extern __shared__ char smem_raw[];
    Smem& s = *reinterpret_cast<Smem*>(smem_raw);
    __shared__ float redM[4][64], redS[4][64];
    int b   = blockIdx.y;
    int m0  = blockIdx.x * 64;
    int tid = threadIdx.x, lane = tid & 31, wid = tid >> 5;
    int wm = wid & 1, wn = wid >> 1;
    int lr = lane >> 2, lc = (lane & 3) * 2;

    float acc[2][6][4] = {};

    // energy = F^T G  (K = 64)
    run_gemm(s, acc, g_Fh + (size_t)(b * 192 + m0) * 64, 64,
             g_Gh + (size_t)b * 64 * BNP, 64, tid, lane, wm, wn);

    // ---- softmax over cols ----
    float pmax[2][2];
#pragma unroll
    for (int mt = 0; mt < 2; mt++)
#pragma unroll
        for (int half = 0; half < 2; half++) {
            float m = -CUDART_INF_F;
#pragma unroll
            for (int t = 0; t < 6; t++)
#pragma unroll
                for (int e = 0; e < 2; e++) {
                    int n = wn * 48 + t * 8 + lc + e;
                    if (n < NTOK) m = fmaxf(m, acc[mt][t][half * 2 + e]);
                }
            pmax[mt][half] = m;
        }
#pragma unroll
    for (int off = 1; off < 4; off <<= 1)
#pragma unroll
        for (int mt = 0; mt < 2; mt++)
#pragma unroll
            for (int half = 0; half < 2; half++)
                pmax[mt][half] = fmaxf(pmax[mt][half],
                    __shfl_xor_sync(0xffffffffu, pmax[mt][half], off, 4));
    if ((lane & 3) == 0) {
#pragma unroll
        for (int mt = 0; mt < 2; mt++)
#pragma unroll
            for (int half = 0; half < 2; half++)
                redM[wn][wm * 32 + mt * 16 + lr + half * 8] = pmax[mt][half];
    }
    __syncthreads();
    float mx[2][2];
#pragma unroll
    for (int mt = 0; mt < 2; mt++)
#pragma unroll
        for (int half = 0; half < 2; half++) {
            int row = wm * 32 + mt * 16 + lr + half * 8;
            mx[mt][half] = fmaxf(fmaxf(redM[0][row], redM[1][row]),
                                 fmaxf(redM[2][row], redM[3][row]));
        }
    float psum[2][2] = {};
#pragma unroll
    for (int mt = 0; mt < 2; mt++)
#pragma unroll
        for (int half = 0; half < 2; half++)
#pragma unroll
            for (int t = 0; t < 6; t++)
#pragma unroll
                for (int e = 0; e < 2; e++) {
                    int n = wn * 48 + t * 8 + lc + e;
                    float ev = (n < NTOK) ?
                        __expf(acc[mt][t][half * 2 + e] - mx[mt][half]) : 0.f;
                    acc[mt][t][half * 2 + e] = ev;
                    psum[mt][half] += ev;
                }
#pragma unroll
    for (int off = 1; off < 4; off <<= 1)
#pragma unroll
        for (int mt = 0; mt < 2; mt++)
#pragma unroll
            for (int half = 0; half < 2; half++)
                psum[mt][half] += __shfl_xor_sync(0xffffffffu, psum[mt][half], off, 4);
    if ((lane & 3) == 0) {
#pragma unroll
        for (int mt = 0; mt < 2; mt++)
#pragma unroll
            for (int half = 0; half < 2; half++)
                redS[wn][wm * 32 + mt * 16 + lr + half * 8] = psum[mt][half];
    }
    __syncthreads();
#pragma unroll
    for (int mt = 0; mt < 2; mt++)
#pragma unroll
        for (int half = 0; half < 2; half++) {
            int row = wm * 32 + mt * 16 + lr + half * 8;
            float inv = 1.f / (redS[0][row] + redS[1][row] + redS[2][row] + redS[3][row]);
#pragma unroll
            for (int t = 0; t < 6; t++)
#pragma unroll
                for (int e = 0; e < 2; e++)
                    acc[mt][t][half * 2 + e] *= inv;
        }
    __syncthreads();

    // += h_w @ f8 (K=256) then u_w @ pool (K=128) — one pipeline, no drain
    Seg sg0 = { g_hwh + (size_t)m0 * 256, 256, g_f8h + (size_t)b * 256 * BNP, 256 };
    Seg sg1 = { g_uwh + (size_t)m0 * 128, 128, g_ph  + (size_t)b * 128 * BNP, 128 };
    run_gemm_seg2(s, acc, sg0, sg1, tid, lane, wm, wn);

    // ---- write S ----
#pragma unroll
    for (int mt = 0; mt < 2; mt++)
#pragma unroll
    for (int half = 0; half < 2; half++) {
        int row = m0 + wm * 32 + mt * 16 + lr + half * 8;
        if (row >= NTOK) continue;
        float bv = h_b[row] + u_b[row];
        size_t ro = (size_t)(b * 192 + row) * BNP;
#pragma unroll
        for (int t = 0; t < 6; t++)
#pragma unroll
            for (int e = 0; e < 2; e++) {
                int n = wn * 48 + t * 8 + lc + e;
                if (n < NTOK)
                    g_Sh[ro + n] = __float2half_rn(acc[mt][t][half * 2 + e] + bv);
            }
    }
}

// ============================================================
// out = gamma * (c_w @ S + c_b) + x     grid (8, BATCH), K = 192
// ============================================================
__global__ __launch_bounds__(256, 3) void out_kernel(const float* __restrict__ c_b,
                                                     const float* __restrict__ x,
                                                     const float* __restrict__ gamma_p,
                                                     float* __restrict__ Out)
{
    extern __shared__ char smem_raw[];
    Smem& s = *reinterpret_cast<Smem*>(smem_raw);
    int b   = blockIdx.y;
    int m0  = blockIdx.x * 64;
    int tid = threadIdx.x, lane = tid & 31, wid = tid >> 5;
    int wm = wid & 1, wn = wid >> 1;
    int lr = lane >> 2, lc = (lane & 3) * 2;

    float acc[2][6][4] = {};
    run_gemm(s, acc, g_cwh + (size_t)m0 * 192, 192,
             g_Sh + (size_t)b * 192 * BNP, 192, tid, lane, wm, wn);

    float gma = *gamma_p;
#pragma unroll
    for (int mt = 0; mt < 2; mt++)
#pragma unroll
    for (int half = 0; half < 2; half++) {
        int m = m0 + wm * 32 + mt * 16 + lr + half * 8;
        float bv = c_b[m];
        const float* xrow = x + (size_t)b * 512 * NTOK + (size_t)m * NTOK;
        float* orow = Out + (size_t)b * 512 * NTOK + (size_t)m * NTOK;
#pragma unroll
        for (int t = 0; t < 6; t++)
#pragma unroll
            for (int e = 0; e < 2; e++) {
                int n = wn * 48 + t * 8 + lc + e;
                if (n < NTOK)
                    orow[n] = fmaf(gma, acc[mt][t][half * 2 + e] + bv, xrow[n]);
            }
    }
}

// ============================================================
extern "C" void kernel_launch(void* const* d_in, const int* in_sizes, int n_in,
                              void* d_out, int out_size)
{
    const float* x    = (const float*)d_in[0];
    const float* f5   = (const float*)d_in[1];
    const float* f8   = (const float*)d_in[2];
    const float* f_w  = (const float*)d_in[3];
    const float* f_b  = (const float*)d_in[4];
    const float* g_w  = (const float*)d_in[5];
    const float* g_b  = (const float*)d_in[6];
    const float* h_w  = (const float*)d_in[7];
    const float* h_b  = (const float*)d_in[8];
    const float* u_w  = (const float*)d_in[9];
    const float* u_b  = (const float*)d_in[10];
    const float* c_w  = (const float*)d_in[11];
    const float* c_b  = (const float*)d_in[12];
    const float* gma  = (const float*)d_in[13];

    float* out = (float*)d_out;

    cudaFuncSetAttribute(fg_kernel,  cudaFuncAttributeMaxDynamicSharedMemorySize, (int)SMEM_BYTES);
    cudaFuncSetAttribute(s_kernel,   cudaFuncAttributeMaxDynamicSharedMemorySize, (int)SMEM_BYTES);
    cudaFuncSetAttribute(out_kernel, cudaFuncAttributeMaxDynamicSharedMemorySize, (int)SMEM_BYTES);

    long long total = (long long)WTOT + XF2 + PTOT;
    prepare_kernel<<<(int)((total + 255) / 256), 256>>>(f_w, g_w, h_w, u_w, c_w, x, f8, f5);
    fg_kernel<<<dim3(2, BATCH), 256, SMEM_BYTES>>>(f_b, g_b);
    s_kernel<<<dim3(3, BATCH), 256, SMEM_BYTES>>>(h_b, u_b);
    out_kernel<<<dim3(8, BATCH), 256, SMEM_BYTES>>>(c_b, x, gma, out);
}

// round 16
// speedup vs baseline: 1.3883x; 1.0160x over previous
#include <cuda_runtime.h>
#include <cuda_fp16.h>
#include <math_constants.h>
#include <cstdint>

#define HW 13
#define NTOK 169
#define BNP 192          // fp16 B-operand column stride
#define BATCH 256

typedef __half hf;

// ---- B-operand planes: [k][BNP] fp16 ----
__device__ __align__(16) hf g_xh [BATCH * 512 * BNP];
__device__ __align__(16) hf g_f8h[BATCH * 256 * BNP];
__device__ __align__(16) hf g_ph [BATCH * 128 * BNP];
__device__ __align__(16) hf g_Gh [BATCH * 64 * BNP];
__device__ __align__(16) hf g_Sh [BATCH * 192 * BNP];   // rows 169+ stay 0
// ---- A-operand planes: [m][K] fp16 ----
__device__ __align__(16) hf g_fwh[64 * 512];
__device__ __align__(16) hf g_gwh[64 * 512];
__device__ __align__(16) hf g_hwh[192 * 256];
__device__ __align__(16) hf g_uwh[192 * 128];
__device__ __align__(16) hf g_cwh[512 * 192];           // cols 176+ stay 0
__device__ __align__(16) hf g_Fh [BATCH * 192 * 64];

// ============================================================
// low-level helpers
// ============================================================
__device__ __forceinline__ unsigned smem_u32(const void* p) {
    return (unsigned)__cvta_generic_to_shared(p);
}
__device__ __forceinline__ void cpa16(void* dst, const void* src) {
    asm volatile("cp.async.cg.shared.global [%0], [%1], 16;"
                 :: "r"(smem_u32(dst)), "l"(src));
}
#define CP_COMMIT()  asm volatile("cp.async.commit_group;")
#define CP_WAIT2()   asm volatile("cp.async.wait_group 2;")

__device__ __forceinline__ void ldsm_x4(unsigned (&r)[4], unsigned a) {
    asm volatile("ldmatrix.sync.aligned.m8n8.x4.shared.b16 {%0,%1,%2,%3}, [%4];"
        : "=r"(r[0]), "=r"(r[1]), "=r"(r[2]), "=r"(r[3]) : "r"(a));
}
__device__ __forceinline__ void ldsm_x4t(unsigned (&r)[4], unsigned a) {
    asm volatile("ldmatrix.sync.aligned.m8n8.x4.trans.shared.b16 {%0,%1,%2,%3}, [%4];"
        : "=r"(r[0]), "=r"(r[1]), "=r"(r[2]), "=r"(r[3]) : "r"(a));
}
__device__ __forceinline__ void mma16816(float (&d)[4], const unsigned (&a)[4],
                                         unsigned b0, unsigned b1) {
    asm volatile("mma.sync.aligned.m16n8k16.row.col.f32.f16.f16.f32 "
        "{%0,%1,%2,%3}, {%4,%5,%6,%7}, {%8,%9}, {%0,%1,%2,%3};"
        : "+f"(d[0]), "+f"(d[1]), "+f"(d[2]), "+f"(d[3])
        : "r"(a[0]), "r"(a[1]), "r"(a[2]), "r"(a[3]), "r"(b0), "r"(b1));
}

// ============================================================
// GEMM: CTA tile 64M x 192N, warp grid 2M x 4N (32M x 48N per warp).
// Pure fp16, 4-stage cp.async pipeline (3 fills in flight).
// ============================================================
struct Smem {
    hf Ah[4][64][40];     // 5120 B per stage
    hf Bh[4][32][200];    // 12800 B per stage
};                         // 71680 B total
#define SMEM_BYTES sizeof(Smem)

__device__ __forceinline__ void fill(Smem& s, int buf,
                                     const hf* __restrict__ Ah, int lda,
                                     const hf* __restrict__ Bh,
                                     int k0, int tid)
{
#pragma unroll
    for (int i = 0; i < 4; i++) {       // 256 A-units + 768 B-units = 1024 16B ops
        int idx = tid + i * 256;
        if (idx < 256) {
            int r = idx >> 2, q = idx & 3;
            cpa16(&s.Ah[buf][r][q * 8], Ah + (size_t)r * lda + k0 + q * 8);
        } else {
            int j = idx - 256;
            int rr = j / 24, q = j - rr * 24;
            cpa16(&s.Bh[buf][rr][q * 8], Bh + (size_t)(k0 + rr) * BNP + q * 8);
        }
    }
}

__device__ __forceinline__ void mma_chunk(float (&acc)[2][6][4], Smem& s, int buf,
                                          int lane, int wm, int wn)
{
    unsigned rsel = lane & 15;
    unsigned csel = (lane >> 4) << 3;
#pragma unroll
    for (int ks = 0; ks < 32; ks += 16) {
        unsigned ah[2][4];
#pragma unroll
        for (int mt = 0; mt < 2; mt++)
            ldsm_x4(ah[mt], smem_u32(&s.Ah[buf][wm * 32 + mt * 16 + rsel][ks + csel]));
#pragma unroll
        for (int g = 0; g < 3; g++) {
            unsigned bh[4];
            ldsm_x4t(bh, smem_u32(&s.Bh[buf][ks + rsel][wn * 48 + g * 16 + csel]));
#pragma unroll
            for (int mt = 0; mt < 2; mt++) {
                mma16816(acc[mt][2 * g],     ah[mt], bh[0], bh[1]);
                mma16816(acc[mt][2 * g + 1], ah[mt], bh[2], bh[3]);
            }
        }
    }
}

// 4-stage pipeline, uniform group count via empty commits:
// prologue: commit groups 0,1,2 (fill or empty).
// iter t: wait_group(2) [group t done], barrier, commit group t+3
//         (fill if in range, else empty), mma(t).
__device__ __forceinline__ void run_gemm(Smem& s, float (&acc)[2][6][4],
                                         const hf* __restrict__ Ah, int lda,
                                         const hf* __restrict__ Bh,
                                         int K, int tid, int lane, int wm, int wn)
{
    int nt = K >> 5;
#pragma unroll
    for (int p = 0; p < 3; p++) {
        if (p < nt) fill(s, p, Ah, lda, Bh, p << 5, tid);
        CP_COMMIT();
    }
    for (int t = 0; t < nt; t++) {
        CP_WAIT2();
        __syncthreads();
        if (t + 3 < nt) fill(s, (t + 3) & 3, Ah, lda, Bh, (t + 3) << 5, tid);
        CP_COMMIT();
        mma_chunk(acc, s, t & 3, lane, wm, wn);
    }
    __syncthreads();
}

// two back-to-back GEMMs through one 4-stage pipeline (no drain between)
struct Seg { const hf* A; int lda; const hf* B; int K; };

__device__ __forceinline__ void run_gemm_seg2(Smem& s, float (&acc)[2][6][4],
                                              Seg s0, Seg s1,
                                              int tid, int lane, int wm, int wn)
{
    int nt0 = s0.K >> 5, nt1 = s1.K >> 5, nt = nt0 + nt1;
    auto fillc = [&](int buf, int c) {
        if (c < nt0) fill(s, buf, s0.A, s0.lda, s0.B, c << 5, tid);
        else         fill(s, buf, s1.A, s1.lda, s1.B, (c - nt0) << 5, tid);
    };
#pragma unroll
    for (int p = 0; p < 3; p++) {
        if (p < nt) fillc(p, p);
        CP_COMMIT();
    }
    for (int t = 0; t < nt; t++) {
        CP_WAIT2();
        __syncthreads();
        if (t + 3 < nt) fillc((t + 3) & 3, t + 3);
        CP_COMMIT();
        mma_chunk(acc, s, t & 3, lane, wm, wn);
    }
    __syncthreads();
}

// ============================================================
// fused prepare: weights + x/f8 convert + antialiased pool
// ============================================================
__constant__ int   c_tap0[HW] = { 0, 1, 3, 5, 7, 9,11,13,15,17,19,21,23};
__constant__ float c_wt[HW][4] = {
    {3.f/7.f, 3.f/7.f, 1.f/7.f, 0.f},
    {0.125f, 0.375f, 0.375f, 0.125f}, {0.125f, 0.375f, 0.375f, 0.125f},
    {0.125f, 0.375f, 0.375f, 0.125f}, {0.125f, 0.375f, 0.375f, 0.125f},
    {0.125f, 0.375f, 0.375f, 0.125f}, {0.125f, 0.375f, 0.375f, 0.125f},
    {0.125f, 0.375f, 0.375f, 0.125f}, {0.125f, 0.375f, 0.375f, 0.125f},
    {0.125f, 0.375f, 0.375f, 0.125f}, {0.125f, 0.375f, 0.375f, 0.125f},
    {0.125f, 0.375f, 0.375f, 0.125f},
    {1.f/7.f, 3.f/7.f, 3.f/7.f, 0.f}
};

#define NW1 (64 * 512)
#define NW2 (64 * 512)
#define NW3 (169 * 256)
#define NW4 (169 * 128)
#define NW5 (512 * 169)
#define WTOT (NW1 + NW2 + NW3 + NW4 + NW5)
#define XROWS (BATCH * 512)
#define FROWS (BATCH * 256)
#define XF2  ((XROWS + FROWS) * 85)
#define PTOT (BATCH * 128 * NTOK)

__global__ __launch_bounds__(256) void prepare_kernel(
    const float* __restrict__ f_w, const float* __restrict__ g_w,
    const float* __restrict__ h_w, const float* __restrict__ u_w,
    const float* __restrict__ c_w,
    const float* __restrict__ x,  const float* __restrict__ f8,
    const float* __restrict__ f5)
{
    int idx = blockIdx.x * 256 + threadIdx.x;
    if (idx < WTOT) {
        float v; hf* dh;
        if (idx < NW1) { v = f_w[idx]; dh = g_fwh + idx; }
        else if ((idx -= NW1) < NW2) { v = g_w[idx]; dh = g_gwh + idx; }
        else if ((idx -= NW2) < NW3) { v = h_w[idx]; dh = g_hwh + idx; }
        else if ((idx -= NW3) < NW4) { v = u_w[idx]; dh = g_uwh + idx; }
        else {
            idx -= NW4;
            int m = idx / 169, k = idx - m * 169;
            v = c_w[idx]; dh = g_cwh + (size_t)m * 192 + k;
        }
        *dh = __float2half_rn(v);
        return;
    }
    idx -= WTOT;
    if (idx < XF2) {
        int row = idx / 85, q = idx - row * 85;
        int n = 2 * q;
        const float* src; hf* bh;
        if (row < XROWS) { src = x;  bh = g_xh; }
        else { row -= XROWS; src = f8; bh = g_f8h; }
        const float* sr = src + (size_t)row * NTOK;
        hf* dr = bh + (size_t)row * BNP;
        if (n + 1 < NTOK) {
            __half2 h2 = __floats2half2_rn(sr[n], sr[n + 1]);
            *(__half2*)&dr[n] = h2;
        } else if (n < NTOK) {
            dr[n] = __float2half_rn(sr[n]);
        }
        return;
    }
    idx -= XF2;
    if (idx < PTOT) {
        int n  = idx % NTOK;
        int bc = idx / NTOK;
        int j = n % HW, i = n / HW;
        const float* src = f5 + (size_t)bc * 26 * 26;
        int r0 = c_tap0[i], cc0 = c_tap0[j];
        float acc = 0.f;
#pragma unroll
        for (int ri = 0; ri < 4; ri++) {
            float wr = c_wt[i][ri];
            if (wr == 0.f) continue;
            int r = r0 + ri;
            float rowv = 0.f;
#pragma unroll
            for (int ci = 0; ci < 4; ci++) {
                float wc = c_wt[j][ci];
                if (wc == 0.f) continue;
                rowv = fmaf(wc, src[r * 26 + cc0 + ci], rowv);
            }
            acc = fmaf(wr, rowv, acc);
        }
        g_ph[(size_t)bc * BNP + n] = __float2half_rn(acc);
    }
}

// ============================================================
// F / G projections: grid (2, BATCH)
// ============================================================
__global__ __launch_bounds__(256, 3) void fg_kernel(const float* __restrict__ f_b,
                                                    const float* __restrict__ g_b)
{
    extern __shared__ char smem_raw[];
    Smem& s = *reinterpret_cast<Smem*>(smem_raw);
    int b    = blockIdx.y;
    bool isG = blockIdx.x != 0;
    int tid = threadIdx.x, lane = tid & 31, wid = tid >> 5;
    int wm = wid & 1, wn = wid >> 1;

    float acc[2][6][4] = {};
    run_gemm(s, acc, isG ? g_gwh : g_fwh, 512,
             g_xh + (size_t)b * 512 * BNP, 512, tid, lane, wm, wn);

    const float* bias = isG ? g_b : f_b;
    int lr = lane >> 2, lc = (lane & 3) * 2;
#pragma unroll
    for (int mt = 0; mt < 2; mt++)
#pragma unroll
    for (int half = 0; half < 2; half++) {
        int m = wm * 32 + mt * 16 + lr + half * 8;
        float bv = bias[m];
#pragma unroll
        for (int t = 0; t < 6; t++) {
#pragma unroll
            for (int e = 0; e < 2; e++) {
                int n = wn * 48 + t * 8 + lc + e;
                if (n >= NTOK) continue;
                float v = acc[mt][t][half * 2 + e] + bv;
                if (isG)
                    g_Gh[(size_t)(b * 64 + m) * BNP + n] = __float2half_rn(v);
                else
                    g_Fh[(size_t)(b * 192 + n) * 64 + m] = __float2half_rn(v);
            }
        }
    }
}

// ============================================================
// S = softmax(F^T G) + h_w@f8 + u_w@pool + bias     grid (3, BATCH)
// ============================================================
__global__ __launch_bounds__(256, 3) void s_kernel(const float* __restrict__ h_b,
                                                   const float* __restrict__ u_b)
{
    extern __shared__ char smem_raw[];
    Smem& s = *reinterpret_cast<Smem*>(smem_raw);
    __shared__ float redM[4][64], redS[4][64];
    int b   = blockIdx.y;
    int m0  = blockIdx.x * 64;
    int tid = threadIdx.x, lane = tid & 31, wid = tid >> 5;
    int wm = wid & 1, wn = wid >> 1;
    int lr = lane >> 2, lc = (lane & 3) * 2;

    float acc[2][6][4] = {};

    // energy = F^T G  (K = 64)
    run_gemm(s, acc, g_Fh + (size_t)(b * 192 + m0) * 64, 64,
             g_Gh + (size_t)b * 64 * BNP, 64, tid, lane, wm, wn);

    // ---- softmax over cols ----
    float pmax[2][2];
#pragma unroll
    for (int mt = 0; mt < 2; mt++)
#pragma unroll
        for (int half = 0; half < 2; half++) {
            float m = -CUDART_INF_F;
#pragma unroll
            for (int t = 0; t < 6; t++)
#pragma unroll
                for (int e = 0; e < 2; e++) {
                    int n = wn * 48 + t * 8 + lc + e;
                    if (n < NTOK) m = fmaxf(m, acc[mt][t][half * 2 + e]);
                }
            pmax[mt][half] = m;
        }
#pragma unroll
    for (int off = 1; off < 4; off <<= 1)
#pragma unroll
        for (int mt = 0; mt < 2; mt++)
#pragma unroll
            for (int half = 0; half < 2; half++)
                pmax[mt][half] = fmaxf(pmax[mt][half],
                    __shfl_xor_sync(0xffffffffu, pmax[mt][half], off, 4));
    if ((lane & 3) == 0) {
#pragma unroll
        for (int mt = 0; mt < 2; mt++)
#pragma unroll
            for (int half = 0; half < 2; half++)
                redM[wn][wm * 32 + mt * 16 + lr + half * 8] = pmax[mt][half];
    }
    __syncthreads();
    float mx[2][2];
#pragma unroll
    for (int mt = 0; mt < 2; mt++)
#pragma unroll
        for (int half = 0; half < 2; half++) {
            int row = wm * 32 + mt * 16 + lr + half * 8;
            mx[mt][half] = fmaxf(fmaxf(redM[0][row], redM[1][row]),
                                 fmaxf(redM[2][row], redM[3][row]));
        }
    float psum[2][2] = {};
#pragma unroll
    for (int mt = 0; mt < 2; mt++)
#pragma unroll
        for (int half = 0; half < 2; half++)
#pragma unroll
            for (int t = 0; t < 6; t++)
#pragma unroll
                for (int e = 0; e < 2; e++) {
                    int n = wn * 48 + t * 8 + lc + e;
                    float ev = (n < NTOK) ?
                        __expf(acc[mt][t][half * 2 + e] - mx[mt][half]) : 0.f;
                    acc[mt][t][half * 2 + e] = ev;
                    psum[mt][half] += ev;
                }
#pragma unroll
    for (int off = 1; off < 4; off <<= 1)
#pragma unroll
        for (int mt = 0; mt < 2; mt++)
#pragma unroll
            for (int half = 0; half < 2; half++)
                psum[mt][half] += __shfl_xor_sync(0xffffffffu, psum[mt][half], off, 4);
    if ((lane & 3) == 0) {
#pragma unroll
        for (int mt = 0; mt < 2; mt++)
#pragma unroll
            for (int half = 0; half < 2; half++)
                redS[wn][wm * 32 + mt * 16 + lr + half * 8] = psum[mt][half];
    }
    __syncthreads();
#pragma unroll
    for (int mt = 0; mt < 2; mt++)
#pragma unroll
        for (int half = 0; half < 2; half++) {
            int row = wm * 32 + mt * 16 + lr + half * 8;
            float inv = 1.f / (redS[0][row] + redS[1][row] + redS[2][row] + redS[3][row]);
#pragma unroll
            for (int t = 0; t < 6; t++)
#pragma unroll
                for (int e = 0; e < 2; e++)
                    acc[mt][t][half * 2 + e] *= inv;
        }
    __syncthreads();

    // += h_w @ f8 (K=256) then u_w @ pool (K=128) — one pipeline
    Seg sg0 = { g_hwh + (size_t)m0 * 256, 256, g_f8h + (size_t)b * 256 * BNP, 256 };
    Seg sg1 = { g_uwh + (size_t)m0 * 128, 128, g_ph  + (size_t)b * 128 * BNP, 128 };
    run_gemm_seg2(s, acc, sg0, sg1, tid, lane, wm, wn);

    // ---- write S ----
#pragma unroll
    for (int mt = 0; mt < 2; mt++)
#pragma unroll
    for (int half = 0; half < 2; half++) {
        int row = m0 + wm * 32 + mt * 16 + lr + half * 8;
        if (row >= NTOK) continue;
        float bv = h_b[row] + u_b[row];
        size_t ro = (size_t)(b * 192 + row) * BNP;
#pragma unroll
        for (int t = 0; t < 6; t++)
#pragma unroll
            for (int e = 0; e < 2; e++) {
                int n = wn * 48 + t * 8 + lc + e;
                if (n < NTOK)
                    g_Sh[ro + n] = __float2half_rn(acc[mt][t][half * 2 + e] + bv);
            }
    }
}

// ============================================================
// out = gamma * (c_w @ S + c_b) + x     grid (8, BATCH), K = 192
// ============================================================
__global__ __launch_bounds__(256, 3) void out_kernel(const float* __restrict__ c_b,
                                                     const float* __restrict__ x,
                                                     const float* __restrict__ gamma_p,
                                                     float* __restrict__ Out)
{
    extern __shared__ char smem_raw[];
    Smem& s = *reinterpret_cast<Smem*>(smem_raw);
    int b   = blockIdx.y;
    int m0  = blockIdx.x * 64;
    int tid = threadIdx.x, lane = tid & 31, wid = tid >> 5;
    int wm = wid & 1, wn = wid >> 1;
    int lr = lane >> 2, lc = (lane & 3) * 2;

    float acc[2][6][4] = {};
    run_gemm(s, acc, g_cwh + (size_t)m0 * 192, 192,
             g_Sh + (size_t)b * 192 * BNP, 192, tid, lane, wm, wn);

    float gma = *gamma_p;
#pragma unroll
    for (int mt = 0; mt < 2; mt++)
#pragma unroll
    for (int half = 0; half < 2; half++) {
        int m = m0 + wm * 32 + mt * 16 + lr + half * 8;
        float bv = c_b[m];
        const float* xrow = x + (size_t)b * 512 * NTOK + (size_t)m * NTOK;
        float* orow = Out + (size_t)b * 512 * NTOK + (size_t)m * NTOK;
#pragma unroll
        for (int t = 0; t < 6; t++)
#pragma unroll
            for (int e = 0; e < 2; e++) {
                int n = wn * 48 + t * 8 + lc + e;
                if (n < NTOK)
                    orow[n] = fmaf(gma, acc[mt][t][half * 2 + e] + bv, xrow[n]);
            }
    }
}

// ============================================================
extern "C" void kernel_launch(void* const* d_in, const int* in_sizes, int n_in,
                              void* d_out, int out_size)
{
    const float* x    = (const float*)d_in[0];
    const float* f5   = (const float*)d_in[1];
    const float* f8   = (const float*)d_in[2];
    const float* f_w  = (const float*)d_in[3];
    const float* f_b  = (const float*)d_in[4];
    const float* g_w  = (const float*)d_in[5];
    const float* g_b  = (const float*)d_in[6];
    const float* h_w  = (const float*)d_in[7];
    const float* h_b  = (const float*)d_in[8];
    const float* u_w  = (const float*)d_in[9];
    const float* u_b  = (const float*)d_in[10];
    const float* c_w  = (const float*)d_in[11];
    const float* c_b  = (const float*)d_in[12];
    const float* gma  = (const float*)d_in[13];

    float* out = (float*)d_out;

    cudaFuncSetAttribute(fg_kernel,  cudaFuncAttributeMaxDynamicSharedMemorySize, (int)SMEM_BYTES);
    cudaFuncSetAttribute(s_kernel,   cudaFuncAttributeMaxDynamicSharedMemorySize, (int)SMEM_BYTES);
    cudaFuncSetAttribute(out_kernel, cudaFuncAttributeMaxDynamicSharedMemorySize, (int)SMEM_BYTES);

    long long total = (long long)WTOT + XF2 + PTOT;
    prepare_kernel<<<(int)((total + 255) / 256), 256>>>(f_w, g_w, h_w, u_w, c_w, x, f8, f5);
    fg_kernel<<<dim3(2, BATCH), 256, SMEM_BYTES>>>(f_b, g_b);
    s_kernel<<<dim3(3, BATCH), 256, SMEM_BYTES>>>(h_b, u_b);
    out_kernel<<<dim3(8, BATCH), 256, SMEM_BYTES>>>(c_b, x, gma, out);
}

// round 17
// speedup vs baseline: 1.3951x; 1.0049x over previous
#include <cuda_runtime.h>
#include <cuda_fp16.h>
#include <math_constants.h>
#include <cstdint>

#define HW 13
#define NTOK 169
#define BNP 192          // fp16 B-operand column stride
#define BATCH 256

typedef __half hf;

// ---- B-operand planes: [k][BNP] fp16 ----
__device__ __align__(16) hf g_xh [BATCH * 512 * BNP];
__device__ __align__(16) hf g_f8h[BATCH * 256 * BNP];
__device__ __align__(16) hf g_ph [BATCH * 128 * BNP];
__device__ __align__(16) hf g_Gh [BATCH * 64 * BNP];
__device__ __align__(16) hf g_Sh [BATCH * 192 * BNP];   // rows 169+ stay 0
// ---- A-operand planes: [m][K] fp16 ----
__device__ __align__(16) hf g_fgw[128 * 512];           // rows 0-63 f_w, 64-127 g_w
__device__ __align__(16) hf g_hwh[192 * 256];
__device__ __align__(16) hf g_uwh[192 * 128];
__device__ __align__(16) hf g_cwh[512 * 192];           // cols 176+ stay 0
__device__ __align__(16) hf g_Fh [BATCH * 192 * 64];

// ============================================================
// low-level helpers
// ============================================================
__device__ __forceinline__ unsigned smem_u32(const void* p) {
    return (unsigned)__cvta_generic_to_shared(p);
}
__device__ __forceinline__ void cpa16(void* dst, const void* src) {
    asm volatile("cp.async.cg.shared.global [%0], [%1], 16;"
                 :: "r"(smem_u32(dst)), "l"(src));
}
#define CP_COMMIT()  asm volatile("cp.async.commit_group;")
#define CP_WAIT2()   asm volatile("cp.async.wait_group 2;")

__device__ __forceinline__ void ldsm_x4(unsigned (&r)[4], unsigned a) {
    asm volatile("ldmatrix.sync.aligned.m8n8.x4.shared.b16 {%0,%1,%2,%3}, [%4];"
        : "=r"(r[0]), "=r"(r[1]), "=r"(r[2]), "=r"(r[3]) : "r"(a));
}
__device__ __forceinline__ void ldsm_x4t(unsigned (&r)[4], unsigned a) {
    asm volatile("ldmatrix.sync.aligned.m8n8.x4.trans.shared.b16 {%0,%1,%2,%3}, [%4];"
        : "=r"(r[0]), "=r"(r[1]), "=r"(r[2]), "=r"(r[3]) : "r"(a));
}
__device__ __forceinline__ void mma16816(float (&d)[4], const unsigned (&a)[4],
                                         unsigned b0, unsigned b1) {
    asm volatile("mma.sync.aligned.m16n8k16.row.col.f32.f16.f16.f32 "
        "{%0,%1,%2,%3}, {%4,%5,%6,%7}, {%8,%9}, {%0,%1,%2,%3};"
        : "+f"(d[0]), "+f"(d[1]), "+f"(d[2]), "+f"(d[3])
        : "r"(a[0]), "r"(a[1]), "r"(a[2]), "r"(a[3]), "r"(b0), "r"(b1));
}

// ============================================================
// 128M x 192N machinery (fg, out): warp grid 2M x 4N, warp tile 64M x 48N
// acc[4][6][4] = 96 regs; per k16/warp: 7 LDSM, 48 HMMA.
// ============================================================
struct Smem128 {
    hf Ah[4][128][40];    // 10240 B per stage
    hf Bh[4][32][200];    // 12800 B per stage
};                         // 92160 B total
#define SMEM128_BYTES sizeof(Smem128)

__device__ __forceinline__ void fill128(Smem128& s, int buf,
                                        const hf* __restrict__ Ah, int lda,
                                        const hf* __restrict__ Bh,
                                        int k0, int tid)
{
#pragma unroll
    for (int i = 0; i < 5; i++) {       // 512 A-units + 768 B-units = 1280 16B ops
        int idx = tid + i * 256;
        if (idx < 512) {
            int r = idx >> 2, q = idx & 3;
            cpa16(&s.Ah[buf][r][q * 8], Ah + (size_t)r * lda + k0 + q * 8);
        } else {
            int j = idx - 512;
            int rr = j / 24, q = j - rr * 24;
            cpa16(&s.Bh[buf][rr][q * 8], Bh + (size_t)(k0 + rr) * BNP + q * 8);
        }
    }
}

__device__ __forceinline__ void mma_chunk128(float (&acc)[4][6][4], Smem128& s, int buf,
                                             int lane, int wm, int wn)
{
    unsigned rsel = lane & 15;
    unsigned csel = (lane >> 4) << 3;
#pragma unroll
    for (int ks = 0; ks < 32; ks += 16) {
        unsigned ah[4][4];
#pragma unroll
        for (int mt = 0; mt < 4; mt++)
            ldsm_x4(ah[mt], smem_u32(&s.Ah[buf][wm * 64 + mt * 16 + rsel][ks + csel]));
#pragma unroll
        for (int g = 0; g < 3; g++) {
            unsigned bh[4];
            ldsm_x4t(bh, smem_u32(&s.Bh[buf][ks + rsel][wn * 48 + g * 16 + csel]));
#pragma unroll
            for (int mt = 0; mt < 4; mt++) {
                mma16816(acc[mt][2 * g],     ah[mt], bh[0], bh[1]);
                mma16816(acc[mt][2 * g + 1], ah[mt], bh[2], bh[3]);
            }
        }
    }
}

__device__ __forceinline__ void run_gemm128(Smem128& s, float (&acc)[4][6][4],
                                            const hf* __restrict__ Ah, int lda,
                                            const hf* __restrict__ Bh,
                                            int K, int tid, int lane, int wm, int wn)
{
    int nt = K >> 5;
#pragma unroll
    for (int p = 0; p < 3; p++) {
        if (p < nt) fill128(s, p, Ah, lda, Bh, p << 5, tid);
        CP_COMMIT();
    }
    for (int t = 0; t < nt; t++) {
        CP_WAIT2();
        __syncthreads();
        if (t + 3 < nt) fill128(s, (t + 3) & 3, Ah, lda, Bh, (t + 3) << 5, tid);
        CP_COMMIT();
        mma_chunk128(acc, s, t & 3, lane, wm, wn);
    }
    __syncthreads();
}

// ============================================================
// 64M x 192N machinery (s_kernel): warp grid 2M x 4N, warp tile 32M x 48N
// ============================================================
struct Smem {
    hf Ah[4][64][40];
    hf Bh[4][32][200];
};                         // 71680 B total
#define SMEM_BYTES sizeof(Smem)

__device__ __forceinline__ void fill(Smem& s, int buf,
                                     const hf* __restrict__ Ah, int lda,
                                     const hf* __restrict__ Bh,
                                     int k0, int tid)
{
#pragma unroll
    for (int i = 0; i < 4; i++) {
        int idx = tid + i * 256;
        if (idx < 256) {
            int r = idx >> 2, q = idx & 3;
            cpa16(&s.Ah[buf][r][q * 8], Ah + (size_t)r * lda + k0 + q * 8);
        } else {
            int j = idx - 256;
            int rr = j / 24, q = j - rr * 24;
            cpa16(&s.Bh[buf][rr][q * 8], Bh + (size_t)(k0 + rr) * BNP + q * 8);
        }
    }
}

__device__ __forceinline__ void mma_chunk(float (&acc)[2][6][4], Smem& s, int buf,
                                          int lane, int wm, int wn)
{
    unsigned rsel = lane & 15;
    unsigned csel = (lane >> 4) << 3;
#pragma unroll
    for (int ks = 0; ks < 32; ks += 16) {
        unsigned ah[2][4];
#pragma unroll
        for (int mt = 0; mt < 2; mt++)
            ldsm_x4(ah[mt], smem_u32(&s.Ah[buf][wm * 32 + mt * 16 + rsel][ks + csel]));
#pragma unroll
        for (int g = 0; g < 3; g++) {
            unsigned bh[4];
            ldsm_x4t(bh, smem_u32(&s.Bh[buf][ks + rsel][wn * 48 + g * 16 + csel]));
#pragma unroll
            for (int mt = 0; mt < 2; mt++) {
                mma16816(acc[mt][2 * g],     ah[mt], bh[0], bh[1]);
                mma16816(acc[mt][2 * g + 1], ah[mt], bh[2], bh[3]);
            }
        }
    }
}

__device__ __forceinline__ void run_gemm(Smem& s, float (&acc)[2][6][4],
                                         const hf* __restrict__ Ah, int lda,
                                         const hf* __restrict__ Bh,
                                         int K, int tid, int lane, int wm, int wn)
{
    int nt = K >> 5;
#pragma unroll
    for (int p = 0; p < 3; p++) {
        if (p < nt) fill(s, p, Ah, lda, Bh, p << 5, tid);
        CP_COMMIT();
    }
    for (int t = 0; t < nt; t++) {
        CP_WAIT2();
        __syncthreads();
        if (t + 3 < nt) fill(s, (t + 3) & 3, Ah, lda, Bh, (t + 3) << 5, tid);
        CP_COMMIT();
        mma_chunk(acc, s, t & 3, lane, wm, wn);
    }
    __syncthreads();
}

struct Seg { const hf* A; int lda; const hf* B; int K; };

__device__ __forceinline__ void run_gemm_seg2(Smem& s, float (&acc)[2][6][4],
                                              Seg s0, Seg s1,
                                              int tid, int lane, int wm, int wn)
{
    int nt0 = s0.K >> 5, nt1 = s1.K >> 5, nt = nt0 + nt1;
    auto fillc = [&](int buf, int c) {
        if (c < nt0) fill(s, buf, s0.A, s0.lda, s0.B, c << 5, tid);
        else         fill(s, buf, s1.A, s1.lda, s1.B, (c - nt0) << 5, tid);
    };
#pragma unroll
    for (int p = 0; p < 3; p++) {
        if (p < nt) fillc(p, p);
        CP_COMMIT();
    }
    for (int t = 0; t < nt; t++) {
        CP_WAIT2();
        __syncthreads();
        if (t + 3 < nt) fillc((t + 3) & 3, t + 3);
        CP_COMMIT();
        mma_chunk(acc, s, t & 3, lane, wm, wn);
    }
    __syncthreads();
}

// ============================================================
// fused prepare: weights + x/f8 convert + antialiased pool
// ============================================================
__constant__ int   c_tap0[HW] = { 0, 1, 3, 5, 7, 9,11,13,15,17,19,21,23};
__constant__ float c_wt[HW][4] = {
    {3.f/7.f, 3.f/7.f, 1.f/7.f, 0.f},
    {0.125f, 0.375f, 0.375f, 0.125f}, {0.125f, 0.375f, 0.375f, 0.125f},
    {0.125f, 0.375f, 0.375f, 0.125f}, {0.125f, 0.375f, 0.375f, 0.125f},
    {0.125f, 0.375f, 0.375f, 0.125f}, {0.125f, 0.375f, 0.375f, 0.125f},
    {0.125f, 0.375f, 0.375f, 0.125f}, {0.125f, 0.375f, 0.375f, 0.125f},
    {0.125f, 0.375f, 0.375f, 0.125f}, {0.125f, 0.375f, 0.375f, 0.125f},
    {0.125f, 0.375f, 0.375f, 0.125f},
    {1.f/7.f, 3.f/7.f, 3.f/7.f, 0.f}
};

#define NW1 (64 * 512)
#define NW2 (64 * 512)
#define NW3 (169 * 256)
#define NW4 (169 * 128)
#define NW5 (512 * 169)
#define WTOT (NW1 + NW2 + NW3 + NW4 + NW5)
#define XROWS (BATCH * 512)
#define FROWS (BATCH * 256)
#define XF2  ((XROWS + FROWS) * 85)
#define PTOT (BATCH * 128 * NTOK)

__global__ __launch_bounds__(256) void prepare_kernel(
    const float* __restrict__ f_w, const float* __restrict__ g_w,
    const float* __restrict__ h_w, const float* __restrict__ u_w,
    const float* __restrict__ c_w,
    const float* __restrict__ x,  const float* __restrict__ f8,
    const float* __restrict__ f5)
{
    int idx = blockIdx.x * 256 + threadIdx.x;
    if (idx < WTOT) {
        float v; hf* dh;
        if (idx < NW1) { v = f_w[idx]; dh = g_fgw + idx; }
        else if ((idx -= NW1) < NW2) { v = g_w[idx]; dh = g_fgw + NW1 + idx; }
        else if ((idx -= NW2) < NW3) { v = h_w[idx]; dh = g_hwh + idx; }
        else if ((idx -= NW3) < NW4) { v = u_w[idx]; dh = g_uwh + idx; }
        else {
            idx -= NW4;
            int m = idx / 169, k = idx - m * 169;
            v = c_w[idx]; dh = g_cwh + (size_t)m * 192 + k;
        }
        *dh = __float2half_rn(v);
        return;
    }
    idx -= WTOT;
    if (idx < XF2) {
        int row = idx / 85, q = idx - row * 85;
        int n = 2 * q;
        const float* src; hf* bh;
        if (row < XROWS) { src = x;  bh = g_xh; }
        else { row -= XROWS; src = f8; bh = g_f8h; }
        const float* sr = src + (size_t)row * NTOK;
        hf* dr = bh + (size_t)row * BNP;
        if (n + 1 < NTOK) {
            __half2 h2 = __floats2half2_rn(sr[n], sr[n + 1]);
            *(__half2*)&dr[n] = h2;
        } else if (n < NTOK) {
            dr[n] = __float2half_rn(sr[n]);
        }
        return;
    }
    idx -= XF2;
    if (idx < PTOT) {
        int n  = idx % NTOK;
        int bc = idx / NTOK;
        int j = n % HW, i = n / HW;
        const float* src = f5 + (size_t)bc * 26 * 26;
        int r0 = c_tap0[i], cc0 = c_tap0[j];
        float acc = 0.f;
#pragma unroll
        for (int ri = 0; ri < 4; ri++) {
            float wr = c_wt[i][ri];
            if (wr == 0.f) continue;
            int r = r0 + ri;
            float rowv = 0.f;
#pragma unroll
            for (int ci = 0; ci < 4; ci++) {
                float wc = c_wt[j][ci];
                if (wc == 0.f) continue;
                rowv = fmaf(wc, src[r * 26 + cc0 + ci], rowv);
            }
            acc = fmaf(wr, rowv, acc);
        }
        g_ph[(size_t)bc * BNP + n] = __float2half_rn(acc);
    }
}

// ============================================================
// F + G projections in one pass: grid (BATCH), A = [f_w ; g_w] 128 rows
// ============================================================
__global__ __launch_bounds__(256, 2) void fg_kernel(const float* __restrict__ f_b,
                                                    const float* __restrict__ g_b)
{
    extern __shared__ char smem_raw[];
    Smem128& s = *reinterpret_cast<Smem128*>(smem_raw);
    int b   = blockIdx.x;
    int tid = threadIdx.x, lane = tid & 31, wid = tid >> 5;
    int wm = wid & 1, wn = wid >> 1;

    float acc[4][6][4] = {};
    run_gemm128(s, acc, g_fgw, 512,
                g_xh + (size_t)b * 512 * BNP, 512, tid, lane, wm, wn);

    int lr = lane >> 2, lc = (lane & 3) * 2;
#pragma unroll
    for (int mt = 0; mt < 4; mt++)
#pragma unroll
    for (int half = 0; half < 2; half++) {
        int m = wm * 64 + mt * 16 + lr + half * 8;   // 0..127
        bool isG = m >= 64;
        int mc = isG ? m - 64 : m;
        float bv = isG ? g_b[mc] : f_b[mc];
#pragma unroll
        for (int t = 0; t < 6; t++) {
#pragma unroll
            for (int e = 0; e < 2; e++) {
                int n = wn * 48 + t * 8 + lc + e;
                if (n >= NTOK) continue;
                float v = acc[mt][t][half * 2 + e] + bv;
                if (isG)
                    g_Gh[(size_t)(b * 64 + mc) * BNP + n] = __float2half_rn(v);
                else
                    g_Fh[(size_t)(b * 192 + n) * 64 + mc] = __float2half_rn(v);
            }
        }
    }
}

// ============================================================
// S = softmax(F^T G) + h_w@f8 + u_w@pool + bias     grid (3, BATCH)
// ============================================================
__global__ __launch_bounds__(256, 3) void s_kernel(const float* __restrict__ h_b,
                                                   const float* __restrict__ u_b)
{
    extern __shared__ char smem_raw[];
    Smem& s = *reinterpret_cast<Smem*>(smem_raw);
    __shared__ float redM[4][64], redS[4][64];
    int b   = blockIdx.y;
    int m0  = blockIdx.x * 64;
    int tid = threadIdx.x, lane = tid & 31, wid = tid >> 5;
    int wm = wid & 1, wn = wid >> 1;
    int lr = lane >> 2, lc = (lane & 3) * 2;

    float acc[2][6][4] = {};

    // energy = F^T G  (K = 64)
    run_gemm(s, acc, g_Fh + (size_t)(b * 192 + m0) * 64, 64,
             g_Gh + (size_t)b * 64 * BNP, 64, tid, lane, wm, wn);

    // ---- softmax over cols ----
    float pmax[2][2];
#pragma unroll
    for (int mt = 0; mt < 2; mt++)
#pragma unroll
        for (int half = 0; half < 2; half++) {
            float m = -CUDART_INF_F;
#pragma unroll
            for (int t = 0; t < 6; t++)
#pragma unroll
                for (int e = 0; e < 2; e++) {
                    int n = wn * 48 + t * 8 + lc + e;
                    if (n < NTOK) m = fmaxf(m, acc[mt][t][half * 2 + e]);
                }
            pmax[mt][half] = m;
        }
#pragma unroll
    for (int off = 1; off < 4; off <<= 1)
#pragma unroll
        for (int mt = 0; mt < 2; mt++)
#pragma unroll
            for (int half = 0; half < 2; half++)
                pmax[mt][half] = fmaxf(pmax[mt][half],
                    __shfl_xor_sync(0xffffffffu, pmax[mt][half], off, 4));
    if ((lane & 3) == 0) {
#pragma unroll
        for (int mt = 0; mt < 2; mt++)
#pragma unroll
            for (int half = 0; half < 2; half++)
                redM[wn][wm * 32 + mt * 16 + lr + half * 8] = pmax[mt][half];
    }
    __syncthreads();
    float mx[2][2];
#pragma unroll
    for (int mt = 0; mt < 2; mt++)
#pragma unroll
        for (int half = 0; half < 2; half++) {
            int row = wm * 32 + mt * 16 + lr + half * 8;
            mx[mt][half] = fmaxf(fmaxf(redM[0][row], redM[1][row]),
                                 fmaxf(redM[2][row], redM[3][row]));
        }
    float psum[2][2] = {};
#pragma unroll
    for (int mt = 0; mt < 2; mt++)
#pragma unroll
        for (int half = 0; half < 2; half++)
#pragma unroll
            for (int t = 0; t < 6; t++)
#pragma unroll
                for (int e = 0; e < 2; e++) {
                    int n = wn * 48 + t * 8 + lc + e;
                    float ev = (n < NTOK) ?
                        __expf(acc[mt][t][half * 2 + e] - mx[mt][half]) : 0.f;
                    acc[mt][t][half * 2 + e] = ev;
                    psum[mt][half] += ev;
                }
#pragma unroll
    for (int off = 1; off < 4; off <<= 1)
#pragma unroll
        for (int mt = 0; mt < 2; mt++)
#pragma unroll
            for (int half = 0; half < 2; half++)
                psum[mt][half] += __shfl_xor_sync(0xffffffffu, psum[mt][half], off, 4);
    if ((lane & 3) == 0) {
#pragma unroll
        for (int mt = 0; mt < 2; mt++)
#pragma unroll
            for (int half = 0; half < 2; half++)
                redS[wn][wm * 32 + mt * 16 + lr + half * 8] = psum[mt][half];
    }
    __syncthreads();
#pragma unroll
    for (int mt = 0; mt < 2; mt++)
#pragma unroll
        for (int half = 0; half < 2; half++) {
            int row = wm * 32 + mt * 16 + lr + half * 8;
            float inv = 1.f / (redS[0][row] + redS[1][row] + redS[2][row] + redS[3][row]);
#pragma unroll
            for (int t = 0; t < 6; t++)
#pragma unroll
                for (int e = 0; e < 2; e++)
                    acc[mt][t][half * 2 + e] *= inv;
        }
    __syncthreads();

    // += h_w @ f8 (K=256) then u_w @ pool (K=128) — one pipeline
    Seg sg0 = { g_hwh + (size_t)m0 * 256, 256, g_f8h + (size_t)b * 256 * BNP, 256 };
    Seg sg1 = { g_uwh + (size_t)m0 * 128, 128, g_ph  + (size_t)b * 128 * BNP, 128 };
    run_gemm_seg2(s, acc, sg0, sg1, tid, lane, wm, wn);

    // ---- write S ----
#pragma unroll
    for (int mt = 0; mt < 2; mt++)
#pragma unroll
    for (int half = 0; half < 2; half++) {
        int row = m0 + wm * 32 + mt * 16 + lr + half * 8;
        if (row >= NTOK) continue;
        float bv = h_b[row] + u_b[row];
        size_t ro = (size_t)(b * 192 + row) * BNP;
#pragma unroll
        for (int t = 0; t < 6; t++)
#pragma unroll
            for (int e = 0; e < 2; e++) {
                int n = wn * 48 + t * 8 + lc + e;
                if (n < NTOK)
                    g_Sh[ro + n] = __float2half_rn(acc[mt][t][half * 2 + e] + bv);
            }
    }
}

// ============================================================
// out = gamma * (c_w @ S + c_b) + x     grid (4, BATCH), K = 192
// ============================================================
__global__ __launch_bounds__(256, 2) void out_kernel(const float* __restrict__ c_b,
                                                     const float* __restrict__ x,
                                                     const float* __restrict__ gamma_p,
                                                     float* __restrict__ Out)
{
    extern __shared__ char smem_raw[];
    Smem128& s = *reinterpret_cast<Smem128*>(smem_raw);
    int b   = blockIdx.y;
    int m0  = blockIdx.x * 128;
    int tid = threadIdx.x, lane = tid & 31, wid = tid >> 5;
    int wm = wid & 1, wn = wid >> 1;
    int lr = lane >> 2, lc = (lane & 3) * 2;

    float acc[4][6][4] = {};
    run_gemm128(s, acc, g_cwh + (size_t)m0 * 192, 192,
                g_Sh + (size_t)b * 192 * BNP, 192, tid, lane, wm, wn);

    float gma = *gamma_p;
#pragma unroll
    for (int mt = 0; mt < 4; mt++)
#pragma unroll
    for (int half = 0; half < 2; half++) {
        int m = m0 + wm * 64 + mt * 16 + lr + half * 8;
        float bv = c_b[m];
        const float* xrow = x + (size_t)b * 512 * NTOK + (size_t)m * NTOK;
        float* orow = Out + (size_t)b * 512 * NTOK + (size_t)m * NTOK;
#pragma unroll
        for (int t = 0; t < 6; t++)
#pragma unroll
            for (int e = 0; e < 2; e++) {
                int n = wn * 48 + t * 8 + lc + e;
                if (n < NTOK)
                    orow[n] = fmaf(gma, acc[mt][t][half * 2 + e] + bv, xrow[n]);
            }
    }
}

// ============================================================
extern "C" void kernel_launch(void* const* d_in, const int* in_sizes, int n_in,
                              void* d_out, int out_size)
{
    const float* x    = (const float*)d_in[0];
    const float* f5   = (const float*)d_in[1];
    const float* f8   = (const float*)d_in[2];
    const float* f_w  = (const float*)d_in[3];
    const float* f_b  = (const float*)d_in[4];
    const float* g_w  = (const float*)d_in[5];
    const float* g_b  = (const float*)d_in[6];
    const float* h_w  = (const float*)d_in[7];
    const float* h_b  = (const float*)d_in[8];
    const float* u_w  = (const float*)d_in[9];
    const float* u_b  = (const float*)d_in[10];
    const float* c_w  = (const float*)d_in[11];
    const float* c_b  = (const float*)d_in[12];
    const float* gma  = (const float*)d_in[13];

    float* out = (float*)d_out;

    cudaFuncSetAttribute(fg_kernel,  cudaFuncAttributeMaxDynamicSharedMemorySize, (int)SMEM128_BYTES);
    cudaFuncSetAttribute(s_kernel,   cudaFuncAttributeMaxDynamicSharedMemorySize, (int)SMEM_BYTES);
    cudaFuncSetAttribute(out_kernel, cudaFuncAttributeMaxDynamicSharedMemorySize, (int)SMEM128_BYTES);

    long long total = (long long)WTOT + XF2 + PTOT;
    prepare_kernel<<<(int)((total + 255) / 256), 256>>>(f_w, g_w, h_w, u_w, c_w, x, f8, f5);
    fg_kernel<<<BATCH, 256, SMEM128_BYTES>>>(f_b, g_b);
    s_kernel<<<dim3(3, BATCH), 256, SMEM_BYTES>>>(h_b, u_b);
    out_kernel<<<dim3(4, BATCH), 256, SMEM128_BYTES>>>(c_b, x, gma, out);
}